// round 3
// baseline (speedup 1.0000x reference)
#include <cuda_runtime.h>
#include <math.h>

#define EMB 128
#define WINDOW 200
#define DK 32
#define NH 8
#define NT 50
#define NB 1024

#define OUT_ELEMS (NB*NT*EMB)          // 6,553,600
#define ATT_ELEMS (NB*NH*NT*WINDOW)    // 81,920,000

// ---------------- scratch (device globals; no runtime allocation) ----------
__device__ float g_qh[NB*NH*NT*DK];       // normalized q  (b,h,t,d)
__device__ float g_kh[NB*NH*WINDOW*DK];   // normalized k  (b,h,c,d)
__device__ float g_vp[NB*NH*WINDOW*DK];   // v projection  (b,h,c,d)
__device__ float g_oh[NB*NT*NH*DK];       // out heads     (b,t,h*32+d)
__device__ float g_wtq[EMB*256];          // At_w transposed: [k][o]
__device__ float g_wtk[EMB*256];          // Ac_w transposed
__device__ float g_wtv[EMB*256];          // Bc_w transposed
__device__ float g_rt [256*EMB];          // R_w transposed:  [o][e]

// ---------------- packed f32x2 FMA (2x fp32 throughput on sm_100a) ---------
// Plain ull locals + mov.b64 pack/unpack: avoids the nvcc ICE from cast
// lvalues in asm operands. mov.b64 between regs is register aliasing (free).
__device__ __forceinline__ float2 ffma2(float2 a, float2 b, float2 c) {
    unsigned long long au, bu, cu, du;
    asm("mov.b64 %0, {%1, %2};" : "=l"(au) : "f"(a.x), "f"(a.y));
    asm("mov.b64 %0, {%1, %2};" : "=l"(bu) : "f"(b.x), "f"(b.y));
    asm("mov.b64 %0, {%1, %2};" : "=l"(cu) : "f"(c.x), "f"(c.y));
    asm("fma.rn.f32x2 %0, %1, %2, %3;" : "=l"(du) : "l"(au), "l"(bu), "l"(cu));
    float2 r;
    asm("mov.b64 {%0, %1}, %2;" : "=f"(r.x), "=f"(r.y) : "l"(du));
    return r;
}

// ---------------- weight transpose prep ------------------------------------
__global__ void transpose_kernel(const float* __restrict__ At,
                                 const float* __restrict__ Ac,
                                 const float* __restrict__ Bc,
                                 const float* __restrict__ R)
{
    int i = blockIdx.x * 256 + threadIdx.x;  // 0..32767
    if (i < 32768) {
        int o = i >> 7;          // 0..255 (row of W)
        int k = i & 127;         // 0..127
        g_wtq[k*256 + o] = At[i];
        g_wtk[k*256 + o] = Ac[i];
        g_wtv[k*256 + o] = Bc[i];
        // R is (128, 256): i = e*256 + oo
        int e  = i >> 8;
        int oo = i & 255;
        g_rt[oo*128 + e] = R[i];
    }
}

// ---------------- projection: Y = X @ W^T + b, optional row-norm per head --
// DST: 0 -> g_qh (norm), 1 -> g_kh (norm), 2 -> g_vp (no norm)
template<int RPB, int DST, bool NORM>
__global__ __launch_bounds__(256)
void proj_kernel(const float* __restrict__ X, const float* __restrict__ bias)
{
    const float* __restrict__ Wt = (DST == 0) ? g_wtq : (DST == 1) ? g_wtk : g_wtv;
    float* __restrict__ Y        = (DST == 0) ? g_qh  : (DST == 1) ? g_kh  : g_vp;

    __shared__ float sx[25][EMB];
    const int row0 = blockIdx.x * 25;

    // cooperative tile load: 25*128 floats = 800 float4, contiguous
    const float4* xg = (const float4*)(X + (long long)row0 * EMB);
    float4* sx4 = (float4*)&sx[0][0];
    #pragma unroll
    for (int i = 0; i < 4; i++) {
        int idx = threadIdx.x + i * 256;
        if (idx < 800) sx4[idx] = xg[idx];
    }
    __syncthreads();

    const int o = threadIdx.x;  // output column (head h = o>>5, dim d = o&31)
    float2 acc[25];
    #pragma unroll
    for (int r = 0; r < 25; r++) acc[r] = make_float2(0.f, 0.f);

    for (int k = 0; k < EMB; k += 4) {
        float w0 = Wt[(k+0)*256 + o];   // coalesced: lanes = consecutive o
        float w1 = Wt[(k+1)*256 + o];
        float w2 = Wt[(k+2)*256 + o];
        float w3 = Wt[(k+3)*256 + o];
        float2 wab = make_float2(w0, w1), wcd = make_float2(w2, w3);
        #pragma unroll
        for (int r = 0; r < 25; r++) {
            float4 x4 = *(const float4*)&sx[r][k];   // broadcast LDS
            acc[r] = ffma2(make_float2(x4.x, x4.y), wab, acc[r]);
            acc[r] = ffma2(make_float2(x4.z, x4.w), wcd, acc[r]);
        }
    }

    const float bo = bias[o];
    const int h = o >> 5;
    const int d = o & 31;
    #pragma unroll
    for (int r = 0; r < 25; r++) {
        float y = acc[r].x + acc[r].y + bo;
        if (NORM) {
            // warp == head: reduce sum of squares over the 32 dims
            float ss = y * y;
            #pragma unroll
            for (int s = 16; s > 0; s >>= 1)
                ss += __shfl_xor_sync(0xffffffffu, ss, s);
            y *= rsqrtf(fmaxf(ss, 1e-24f));
        }
        const int row = row0 + r;
        const int bb  = row / RPB;
        const int cc  = row - bb * RPB;
        Y[(((long long)bb * NH + h) * RPB + cc) * DK + d] = y;
    }
}

// ---------------- fused attention per (b,h), two 25-row t-passes -----------
// static smem: 25600 + 3200 + 20000 = 48800 bytes < 48KB? 48800 < 49152 OK
#define TP 25
__global__ __launch_bounds__(256)
void att_kernel(const float* __restrict__ pos_bias,
                float* __restrict__ att_out, int write_att)
{
    __shared__ float svp[WINDOW * DK];   // 6400 floats
    __shared__ float sq [TP * DK];       // 800 floats
    __shared__ float S  [TP * WINDOW];   // 5000 floats

    const int bh = blockIdx.x;       // b*8 + h
    const int b  = bh >> 3;
    const int h  = bh & 7;

    const float* kh = g_kh + (long long)bh * WINDOW * DK;
    const float* vp = g_vp + (long long)bh * WINDOW * DK;
    const float* qh = g_qh + (long long)bh * NT * DK;

    // load v tile into smem once (contiguous, coalesced)
    {
        const float4* vg = (const float4*)vp;
        float4* sv4 = (float4*)svp;
        #pragma unroll
        for (int i = 0; i < 7; i++) {
            int idx = threadIdx.x + i * 256;
            if (idx < 1600) sv4[idx] = vg[idx];
        }
    }

    // k row for this thread stays in registers across both passes
    const int c = threadIdx.x;
    float4 kc[8];
    float pb = 0.f;
    if (c < WINDOW) {
        const float4* kg = (const float4*)(kh + c * DK);
        #pragma unroll
        for (int j = 0; j < 8; j++) kc[j] = kg[j];
        pb = pos_bias[c];
    }

    const int warp = threadIdx.x >> 5;
    const int lane = threadIdx.x & 31;
    const int dg   = threadIdx.x & 7;   // group of 4 dims
    const int trow = threadIdx.x >> 3;  // 0..31
    const float4* v4 = (const float4*)svp;

    #pragma unroll
    for (int pass = 0; pass < 2; pass++) {
        const int t0 = pass * TP;

        __syncthreads();   // prior pass done with sq/S (and v load visible)

        // load q tile for this pass: 25*32 = 800 floats = 200 float4
        {
            const float4* qg = (const float4*)(qh + t0 * DK);
            float4* sq4 = (float4*)sq;
            if (threadIdx.x < 200) sq4[threadIdx.x] = qg[threadIdx.x];
        }
        __syncthreads();

        // ---- scores: S[t][c] = qhat(t)·khat(c) + pos_bias[c] ----
        if (c < WINDOW) {
            for (int t = 0; t < TP; t++) {
                float2 a = make_float2(0.f, 0.f);
                const float4* q4 = (const float4*)(sq + t * DK);
                #pragma unroll
                for (int j = 0; j < 8; j++) {
                    float4 q = q4[j];   // broadcast LDS
                    a = ffma2(make_float2(q.x, q.y), make_float2(kc[j].x, kc[j].y), a);
                    a = ffma2(make_float2(q.z, q.w), make_float2(kc[j].z, kc[j].w), a);
                }
                S[t * WINDOW + c] = a.x + a.y + pb;
            }
        }
        __syncthreads();

        // ---- softmax: one warp per row ----
        for (int t = warp; t < TP; t += 8) {
            float v[7];
            #pragma unroll
            for (int j = 0; j < 7; j++) {
                int cc = lane + 32 * j;
                v[j] = (cc < WINDOW) ? S[t * WINDOW + cc] : -1e30f;
            }
            float mx = v[0];
            #pragma unroll
            for (int j = 1; j < 7; j++) mx = fmaxf(mx, v[j]);
            #pragma unroll
            for (int s = 16; s > 0; s >>= 1)
                mx = fmaxf(mx, __shfl_xor_sync(0xffffffffu, mx, s));
            float sum = 0.f;
            #pragma unroll
            for (int j = 0; j < 7; j++) { v[j] = __expf(v[j] - mx); sum += v[j]; }
            #pragma unroll
            for (int s = 16; s > 0; s >>= 1)
                sum += __shfl_xor_sync(0xffffffffu, sum, s);
            const float inv = 1.0f / sum;
            #pragma unroll
            for (int j = 0; j < 7; j++) {
                int cc = lane + 32 * j;
                if (cc < WINDOW) {
                    float a = v[j] * inv;
                    S[t * WINDOW + cc] = a;
                    if (write_att)
                        att_out[((long long)bh * NT + (t0 + t)) * WINDOW + cc] = a;
                }
            }
        }
        __syncthreads();

        // ---- out_heads[t][d] = sum_c att[t][c] * v[c][d] ----
        if (trow < TP) {
            const int t = trow;
            float2 axy = make_float2(0.f, 0.f), azw = make_float2(0.f, 0.f);
            const float* Srow = S + t * WINDOW;
            for (int c0 = 0; c0 < WINDOW; c0 += 2) {
                float2 s2 = *(const float2*)(Srow + c0);
                float4 v0 = v4[(c0    ) * 8 + dg];
                float4 v1 = v4[(c0 + 1) * 8 + dg];
                axy = ffma2(make_float2(s2.x, s2.x), make_float2(v0.x, v0.y), axy);
                azw = ffma2(make_float2(s2.x, s2.x), make_float2(v0.z, v0.w), azw);
                axy = ffma2(make_float2(s2.y, s2.y), make_float2(v1.x, v1.y), axy);
                azw = ffma2(make_float2(s2.y, s2.y), make_float2(v1.z, v1.w), azw);
            }
            float4 o4 = make_float4(axy.x, axy.y, azw.x, azw.y);
            *(float4*)(g_oh + ((long long)b * NT + (t0 + t)) * (NH * DK) + h * DK + dg * 4) = o4;
        }
    }
}

// ---------------- final projection: out = oh @ R^T + Rb --------------------
__global__ __launch_bounds__(256)
void out_kernel(const float* __restrict__ Rb, float* __restrict__ out)
{
    __shared__ float sx[25 * 256];
    __shared__ float pbuf[25 * 128];
    const int row0 = blockIdx.x * 25;

    const float4* xg = (const float4*)(g_oh + (long long)row0 * 256);
    float4* sx4 = (float4*)sx;
    #pragma unroll
    for (int i = 0; i < 7; i++) {   // 25*64 = 1600 float4
        int idx = threadIdx.x + i * 256;
        if (idx < 1600) sx4[idx] = xg[idx];
    }
    __syncthreads();

    const int e    = threadIdx.x & 127;
    const int half = threadIdx.x >> 7;   // split K=256 across 2 thread groups
    float2 acc[25];
    #pragma unroll
    for (int r = 0; r < 25; r++) acc[r] = make_float2(0.f, 0.f);

    const int k0 = half * 128;
    for (int k = 0; k < 128; k += 4) {
        const int kk = k0 + k;
        float w0 = g_rt[(kk+0)*128 + e];   // coalesced
        float w1 = g_rt[(kk+1)*128 + e];
        float w2 = g_rt[(kk+2)*128 + e];
        float w3 = g_rt[(kk+3)*128 + e];
        float2 wab = make_float2(w0, w1), wcd = make_float2(w2, w3);
        #pragma unroll
        for (int r = 0; r < 25; r++) {
            float4 x4 = *(const float4*)&sx[r*256 + kk];
            acc[r] = ffma2(make_float2(x4.x, x4.y), wab, acc[r]);
            acc[r] = ffma2(make_float2(x4.z, x4.w), wcd, acc[r]);
        }
    }

    if (half == 1) {
        #pragma unroll
        for (int r = 0; r < 25; r++) pbuf[r*128 + e] = acc[r].x + acc[r].y;
    }
    __syncthreads();
    if (half == 0) {
        const float bo = Rb[e];
        #pragma unroll
        for (int r = 0; r < 25; r++) {
            out[(long long)(row0 + r) * 128 + e] =
                acc[r].x + acc[r].y + pbuf[r*128 + e] + bo;
        }
    }
}

// ---------------- launch: kernel launches ONLY (graph-capture safe) --------
extern "C" void kernel_launch(void* const* d_in, const int* in_sizes, int n_in,
                              void* d_out, int out_size)
{
    const float* queries  = (const float*)d_in[0];
    const float* keys     = (const float*)d_in[1];
    const float* values   = (const float*)d_in[2];
    const float* At_w     = (const float*)d_in[3];
    const float* At_b     = (const float*)d_in[4];
    const float* Ac_w     = (const float*)d_in[5];
    const float* Ac_b     = (const float*)d_in[6];
    const float* Bc_w     = (const float*)d_in[7];
    const float* Bc_b     = (const float*)d_in[8];
    const float* pos_bias = (const float*)d_in[9];
    const float* R_w      = (const float*)d_in[10];
    const float* R_b      = (const float*)d_in[11];
    float* out = (float*)d_out;

    transpose_kernel<<<128, 256>>>(At_w, Ac_w, Bc_w, R_w);

    proj_kernel<NT,     0, true ><<<NB*NT/25,     256>>>(queries, At_b);
    proj_kernel<WINDOW, 1, true ><<<NB*WINDOW/25, 256>>>(keys,    Ac_b);
    proj_kernel<WINDOW, 2, false><<<NB*WINDOW/25, 256>>>(values,  Bc_b);

    const long long need = (long long)OUT_ELEMS + (long long)ATT_ELEMS;
    const int write_att = ((long long)out_size >= need) ? 1 : 0;
    att_kernel<<<NB*NH, 256>>>(pos_bias, out + OUT_ELEMS, write_att);

    out_kernel<<<NB*NT/25, 256>>>(R_b, out);
}

// round 4
// speedup vs baseline: 1.0496x; 1.0496x over previous
#include <cuda_runtime.h>
#include <math.h>

#define EMB 128
#define WINDOW 200
#define DK 32
#define NH 8
#define NT 50
#define NB 1024

#define OUT_ELEMS (NB*NT*EMB)          // 6,553,600
#define ATT_ELEMS (NB*NH*NT*WINDOW)    // 81,920,000

// ---------------- scratch (device globals; no runtime allocation) ----------
__device__ float g_qh[NB*NH*NT*DK];       // q projection (unnormalized)  (b,h,t,d)
__device__ float g_kh[NB*NH*WINDOW*DK];   // k projection (unnormalized)  (b,h,c,d)
__device__ float g_vp[NB*NH*WINDOW*DK];   // v projection  (b,h,c,d)
__device__ float g_oh[NB*NT*NH*DK];       // out heads     (b,t,h*32+d)
__device__ float g_rt [256*EMB];          // R_w transposed:  [o][e]

// ---------------- packed f32x2 FMA (2x fp32 throughput on sm_100a) ---------
__device__ __forceinline__ float2 ffma2(float2 a, float2 b, float2 c) {
    unsigned long long au, bu, cu, du;
    asm("mov.b64 %0, {%1, %2};" : "=l"(au) : "f"(a.x), "f"(a.y));
    asm("mov.b64 %0, {%1, %2};" : "=l"(bu) : "f"(b.x), "f"(b.y));
    asm("mov.b64 %0, {%1, %2};" : "=l"(cu) : "f"(c.x), "f"(c.y));
    asm("fma.rn.f32x2 %0, %1, %2, %3;" : "=l"(du) : "l"(au), "l"(bu), "l"(cu));
    float2 r;
    asm("mov.b64 {%0, %1}, %2;" : "=f"(r.x), "=f"(r.y) : "l"(du));
    return r;
}

// ---------------- R transpose prep ------------------------------------------
__global__ void transpose_R(const float* __restrict__ R)
{
    int i = blockIdx.x * 256 + threadIdx.x;  // 0..32767
    if (i < 32768) {
        int e  = i >> 8;      // R is (128, 256)
        int oo = i & 255;
        g_rt[oo*128 + e] = R[i];
    }
}

// ---------------- projection GEMM: Y = X @ W^T + b --------------------------
// W is original nn.Linear layout (256, 128) = [o][k].
// Block: 256 threads, 32 rows x 256 outputs. Thread: 4 rows x 8 outputs
// (o = lane + 32*j -> j = head, lane = dim). K tiled by 32.
// DST: 0 -> g_qh, 1 -> g_kh, 2 -> g_vp
template<int RPB, int DST>
__global__ __launch_bounds__(256)
void proj_kernel(const float* __restrict__ X, const float* __restrict__ W,
                 const float* __restrict__ bias)
{
    float* __restrict__ Y = (DST == 0) ? g_qh : (DST == 1) ? g_kh : g_vp;

    __shared__ float  sx[32 * EMB];     // 16 KB: full X tile (32 rows x 128 k)
    __shared__ float4 sw4[256 * 8];     // 32 KB: W k-tile [o][chunk], XOR swizzled

    const int row0 = blockIdx.x * 32;
    const int warp = threadIdx.x >> 5;
    const int lane = threadIdx.x & 31;
    const int swz  = lane & 7;

    // load X tile once: 32*128 floats = 1024 float4, contiguous
    {
        const float4* xg = (const float4*)(X + (long long)row0 * EMB);
        float4* sx4 = (float4*)sx;
        #pragma unroll
        for (int i = 0; i < 4; i++)
            sx4[threadIdx.x + i * 256] = xg[threadIdx.x + i * 256];
    }

    // bias for this thread's 8 output columns
    float bj[8];
    #pragma unroll
    for (int j = 0; j < 8; j++) bj[j] = bias[lane + 32 * j];

    float2 acc[4][8];
    #pragma unroll
    for (int i = 0; i < 4; i++)
        #pragma unroll
        for (int j = 0; j < 8; j++) acc[i][j] = make_float2(0.f, 0.f);

    const float4* wg = (const float4*)W;   // [o][k/4]: 32 float4 per o-row
    const int rbase = warp << 2;

    for (int kt = 0; kt < 4; kt++) {
        __syncthreads();   // previous tile's sw4 reads done (also covers sx on kt=0)
        // load W k-tile: 2048 float4, swizzled into [o][c ^ (o&7)]
        #pragma unroll
        for (int i = 0; i < 8; i++) {
            int idx = threadIdx.x + i * 256;   // 0..2047
            int o = idx >> 3, c = idx & 7;
            sw4[o * 8 + (c ^ (o & 7))] = wg[o * 32 + kt * 8 + c];
        }
        __syncthreads();

        #pragma unroll
        for (int chunk = 0; chunk < 8; chunk++) {
            float4 xr[4];
            #pragma unroll
            for (int i = 0; i < 4; i++)
                xr[i] = *(const float4*)&sx[(rbase + i) * EMB + kt * 32 + chunk * 4];
            #pragma unroll
            for (int j = 0; j < 8; j++) {
                const int o = lane + 32 * j;
                float4 w4 = sw4[o * 8 + (chunk ^ swz)];
                #pragma unroll
                for (int i = 0; i < 4; i++) {
                    acc[i][j] = ffma2(make_float2(xr[i].x, xr[i].y),
                                      make_float2(w4.x, w4.y), acc[i][j]);
                    acc[i][j] = ffma2(make_float2(xr[i].z, xr[i].w),
                                      make_float2(w4.z, w4.w), acc[i][j]);
                }
            }
        }
    }

    // epilogue: add bias, scatter to (b, h, row_in_seq, d) layout
    #pragma unroll
    for (int i = 0; i < 4; i++) {
        const int row = row0 + rbase + i;
        const int bb  = row / RPB;
        const int cc  = row - bb * RPB;
        #pragma unroll
        for (int j = 0; j < 8; j++) {
            float y = acc[i][j].x + acc[i][j].y + bj[j];
            Y[(((long long)bb * NH + j) * RPB + cc) * DK + lane] = y;
        }
    }
}

// ---------------- fused attention per (b,h), two 25-row t-passes -----------
// q/k normalization happens here (cheap): k rows are register-resident per
// thread; q rows normalized in smem. smem: 6400+800+5000+32 floats = 48928 B.
#define TP 25
__global__ __launch_bounds__(256)
void att_kernel(const float* __restrict__ pos_bias,
                float* __restrict__ att_out, int write_att)
{
    __shared__ float svp[WINDOW * DK];   // 6400 floats
    __shared__ float sq [TP * DK];       // 800 floats
    __shared__ float S  [TP * WINDOW];   // 5000 floats
    __shared__ float sqs[32];            // q row scales

    const int bh = blockIdx.x;       // b*8 + h
    const int b  = bh >> 3;
    const int h  = bh & 7;

    const float* kh = g_kh + (long long)bh * WINDOW * DK;
    const float* vp = g_vp + (long long)bh * WINDOW * DK;
    const float* qh = g_qh + (long long)bh * NT * DK;

    // load v tile into smem once (contiguous, coalesced)
    {
        const float4* vg = (const float4*)vp;
        float4* sv4 = (float4*)svp;
        #pragma unroll
        for (int i = 0; i < 7; i++) {
            int idx = threadIdx.x + i * 256;
            if (idx < 1600) sv4[idx] = vg[idx];
        }
    }

    // k row for this thread: load + normalize in registers
    const int c = threadIdx.x;
    float4 kc[8];
    float pb = 0.f;
    if (c < WINDOW) {
        const float4* kg = (const float4*)(kh + c * DK);
        float ss = 0.f;
        #pragma unroll
        for (int j = 0; j < 8; j++) {
            kc[j] = kg[j];
            ss += kc[j].x*kc[j].x + kc[j].y*kc[j].y + kc[j].z*kc[j].z + kc[j].w*kc[j].w;
        }
        const float sc = rsqrtf(fmaxf(ss, 1e-24f));
        #pragma unroll
        for (int j = 0; j < 8; j++) {
            kc[j].x *= sc; kc[j].y *= sc; kc[j].z *= sc; kc[j].w *= sc;
        }
        pb = pos_bias[c];
    }

    const int warp = threadIdx.x >> 5;
    const int lane = threadIdx.x & 31;
    const int dg   = threadIdx.x & 7;   // group of 4 dims
    const int trow = threadIdx.x >> 3;  // 0..31
    const float4* v4 = (const float4*)svp;

    #pragma unroll
    for (int pass = 0; pass < 2; pass++) {
        const int t0 = pass * TP;

        __syncthreads();   // prior pass done with sq/S (and v load visible)

        // load q tile for this pass: 25*32 = 800 floats = 200 float4
        {
            const float4* qg = (const float4*)(qh + t0 * DK);
            float4* sq4 = (float4*)sq;
            if (threadIdx.x < 200) sq4[threadIdx.x] = qg[threadIdx.x];
        }
        __syncthreads();

        // q row norms (25 threads, 8 LDS.128 each)
        if (threadIdx.x < TP) {
            const float4* r4 = (const float4*)(sq + threadIdx.x * DK);
            float ss = 0.f;
            #pragma unroll
            for (int j = 0; j < 8; j++) {
                float4 q = r4[j];
                ss += q.x*q.x + q.y*q.y + q.z*q.z + q.w*q.w;
            }
            sqs[threadIdx.x] = rsqrtf(fmaxf(ss, 1e-24f));
        }
        __syncthreads();
        if (threadIdx.x < 200) {
            float4* sq4 = (float4*)sq;
            float4 q = sq4[threadIdx.x];
            const float sc = sqs[threadIdx.x >> 3];
            q.x *= sc; q.y *= sc; q.z *= sc; q.w *= sc;
            sq4[threadIdx.x] = q;
        }
        __syncthreads();

        // ---- scores: S[t][c] = qhat(t)·khat(c) + pos_bias[c] ----
        if (c < WINDOW) {
            for (int t = 0; t < TP; t++) {
                float2 a = make_float2(0.f, 0.f);
                const float4* q4 = (const float4*)(sq + t * DK);
                #pragma unroll
                for (int j = 0; j < 8; j++) {
                    float4 q = q4[j];   // broadcast LDS
                    a = ffma2(make_float2(q.x, q.y), make_float2(kc[j].x, kc[j].y), a);
                    a = ffma2(make_float2(q.z, q.w), make_float2(kc[j].z, kc[j].w), a);
                }
                S[t * WINDOW + c] = a.x + a.y + pb;
            }
        }
        __syncthreads();

        // ---- softmax: one warp per row ----
        for (int t = warp; t < TP; t += 8) {
            float v[7];
            #pragma unroll
            for (int j = 0; j < 7; j++) {
                int cc = lane + 32 * j;
                v[j] = (cc < WINDOW) ? S[t * WINDOW + cc] : -1e30f;
            }
            float mx = v[0];
            #pragma unroll
            for (int j = 1; j < 7; j++) mx = fmaxf(mx, v[j]);
            #pragma unroll
            for (int s = 16; s > 0; s >>= 1)
                mx = fmaxf(mx, __shfl_xor_sync(0xffffffffu, mx, s));
            float sum = 0.f;
            #pragma unroll
            for (int j = 0; j < 7; j++) { v[j] = __expf(v[j] - mx); sum += v[j]; }
            #pragma unroll
            for (int s = 16; s > 0; s >>= 1)
                sum += __shfl_xor_sync(0xffffffffu, sum, s);
            const float inv = 1.0f / sum;
            #pragma unroll
            for (int j = 0; j < 7; j++) {
                int cc = lane + 32 * j;
                if (cc < WINDOW) {
                    float a = v[j] * inv;
                    S[t * WINDOW + cc] = a;
                    if (write_att)
                        att_out[((long long)bh * NT + (t0 + t)) * WINDOW + cc] = a;
                }
            }
        }
        __syncthreads();

        // ---- out_heads[t][d] = sum_c att[t][c] * v[c][d] ----
        if (trow < TP) {
            const int t = trow;
            float2 axy = make_float2(0.f, 0.f), azw = make_float2(0.f, 0.f);
            const float* Srow = S + t * WINDOW;
            for (int c0 = 0; c0 < WINDOW; c0 += 2) {
                float2 s2 = *(const float2*)(Srow + c0);
                float4 v0 = v4[(c0    ) * 8 + dg];
                float4 v1 = v4[(c0 + 1) * 8 + dg];
                axy = ffma2(make_float2(s2.x, s2.x), make_float2(v0.x, v0.y), axy);
                azw = ffma2(make_float2(s2.x, s2.x), make_float2(v0.z, v0.w), azw);
                axy = ffma2(make_float2(s2.y, s2.y), make_float2(v1.x, v1.y), axy);
                azw = ffma2(make_float2(s2.y, s2.y), make_float2(v1.z, v1.w), azw);
            }
            float4 o4 = make_float4(axy.x, axy.y, azw.x, azw.y);
            *(float4*)(g_oh + ((long long)b * NT + (t0 + t)) * (NH * DK) + h * DK + dg * 4) = o4;
        }
    }
}

// ---------------- final projection: out = oh @ R^T + Rb --------------------
__global__ __launch_bounds__(256)
void out_kernel(const float* __restrict__ Rb, float* __restrict__ out)
{
    __shared__ float sx[25 * 256];
    __shared__ float pbuf[25 * 128];
    const int row0 = blockIdx.x * 25;

    const float4* xg = (const float4*)(g_oh + (long long)row0 * 256);
    float4* sx4 = (float4*)sx;
    #pragma unroll
    for (int i = 0; i < 7; i++) {   // 25*64 = 1600 float4
        int idx = threadIdx.x + i * 256;
        if (idx < 1600) sx4[idx] = xg[idx];
    }
    __syncthreads();

    const int e    = threadIdx.x & 127;
    const int half = threadIdx.x >> 7;   // split K=256 across 2 thread groups
    float2 acc[25];
    #pragma unroll
    for (int r = 0; r < 25; r++) acc[r] = make_float2(0.f, 0.f);

    const int k0 = half * 128;
    for (int k = 0; k < 128; k += 4) {
        const int kk = k0 + k;
        float w0 = g_rt[(kk+0)*128 + e];   // coalesced
        float w1 = g_rt[(kk+1)*128 + e];
        float w2 = g_rt[(kk+2)*128 + e];
        float w3 = g_rt[(kk+3)*128 + e];
        float2 wab = make_float2(w0, w1), wcd = make_float2(w2, w3);
        #pragma unroll
        for (int r = 0; r < 25; r++) {
            float4 x4 = *(const float4*)&sx[r*256 + kk];
            acc[r] = ffma2(make_float2(x4.x, x4.y), wab, acc[r]);
            acc[r] = ffma2(make_float2(x4.z, x4.w), wcd, acc[r]);
        }
    }

    if (half == 1) {
        #pragma unroll
        for (int r = 0; r < 25; r++) pbuf[r*128 + e] = acc[r].x + acc[r].y;
    }
    __syncthreads();
    if (half == 0) {
        const float bo = Rb[e];
        #pragma unroll
        for (int r = 0; r < 25; r++) {
            out[(long long)(row0 + r) * 128 + e] =
                acc[r].x + acc[r].y + pbuf[r*128 + e] + bo;
        }
    }
}

// ---------------- launch: kernel launches ONLY (graph-capture safe) --------
extern "C" void kernel_launch(void* const* d_in, const int* in_sizes, int n_in,
                              void* d_out, int out_size)
{
    const float* queries  = (const float*)d_in[0];
    const float* keys     = (const float*)d_in[1];
    const float* values   = (const float*)d_in[2];
    const float* At_w     = (const float*)d_in[3];
    const float* At_b     = (const float*)d_in[4];
    const float* Ac_w     = (const float*)d_in[5];
    const float* Ac_b     = (const float*)d_in[6];
    const float* Bc_w     = (const float*)d_in[7];
    const float* Bc_b     = (const float*)d_in[8];
    const float* pos_bias = (const float*)d_in[9];
    const float* R_w      = (const float*)d_in[10];
    const float* R_b      = (const float*)d_in[11];
    float* out = (float*)d_out;

    transpose_R<<<128, 256>>>(R_w);

    proj_kernel<NT,     0><<<NB*NT/32,     256>>>(queries, At_w, At_b);
    proj_kernel<WINDOW, 1><<<NB*WINDOW/32, 256>>>(keys,    Ac_w, Ac_b);
    proj_kernel<WINDOW, 2><<<NB*WINDOW/32, 256>>>(values,  Bc_w, Bc_b);

    const long long need = (long long)OUT_ELEMS + (long long)ATT_ELEMS;
    const int write_att = ((long long)out_size >= need) ? 1 : 0;
    att_kernel<<<NB*NH, 256>>>(pos_bias, out + OUT_ELEMS, write_att);

    out_kernel<<<NB*NT/25, 256>>>(R_b, out);
}

// round 6
// speedup vs baseline: 1.4556x; 1.3868x over previous
#include <cuda_runtime.h>
#include <cuda_bf16.h>
#include <math.h>
#include <stdint.h>

#define EMB 128
#define WINDOW 200
#define DK 32
#define NH 8
#define NT 50
#define NB 1024

#define OUT_ELEMS (NB*NT*EMB)          // 6,553,600
#define ATT_ELEMS (NB*NH*NT*WINDOW)    // 81,920,000

// ---------------- scratch (device globals; no runtime allocation) ----------
__device__ float g_qh[NB*NH*NT*DK];       // q projection  (b,h,t,d)
__device__ float g_kh[NB*NH*WINDOW*DK];   // k projection  (b,h,c,d)
__device__ float g_vp[NB*NH*WINDOW*DK];   // v projection  (b,h,c,d)
__device__ float g_oh[NB*NT*NH*DK];       // out heads     (b,t,h*32+d)
__device__ float g_rt [256*EMB];          // R_w transposed:  [o][e]
__device__ __nv_bfloat16 g_wbhi[3*256*EMB];  // W hi bf16, [o][k] k-major
__device__ __nv_bfloat16 g_wblo[3*256*EMB];  // W lo residual bf16

// ================= helpers ==================================================
__device__ __forceinline__ uint32_t smem_u32(const void* p) {
    uint32_t a;
    asm("{ .reg .u64 t; cvta.to.shared.u64 t, %1; cvt.u32.u64 %0, t; }"
        : "=r"(a) : "l"(p));
    return a;
}

// packed f32x2 FMA (for att / out kernels)
__device__ __forceinline__ float2 ffma2(float2 a, float2 b, float2 c) {
    unsigned long long au, bu, cu, du;
    asm("mov.b64 %0, {%1, %2};" : "=l"(au) : "f"(a.x), "f"(a.y));
    asm("mov.b64 %0, {%1, %2};" : "=l"(bu) : "f"(b.x), "f"(b.y));
    asm("mov.b64 %0, {%1, %2};" : "=l"(cu) : "f"(c.x), "f"(c.y));
    asm("fma.rn.f32x2 %0, %1, %2, %3;" : "=l"(du) : "l"(au), "l"(bu), "l"(cu));
    float2 r;
    asm("mov.b64 {%0, %1}, %2;" : "=f"(r.x), "=f"(r.y) : "l"(du));
    return r;
}

#define LDSM_X4(d, addr) \
    asm volatile("ldmatrix.sync.aligned.m8n8.x4.shared.b16 {%0,%1,%2,%3}, [%4];" \
        : "=r"((d)[0]), "=r"((d)[1]), "=r"((d)[2]), "=r"((d)[3]) : "r"(addr))

#define MMA_BF16(c, a, b) \
    asm volatile("mma.sync.aligned.m16n8k16.row.col.f32.bf16.bf16.f32 " \
        "{%0,%1,%2,%3}, {%4,%5,%6,%7}, {%8,%9}, {%0,%1,%2,%3};" \
        : "+f"((c)[0]), "+f"((c)[1]), "+f"((c)[2]), "+f"((c)[3]) \
        : "r"((a)[0]), "r"((a)[1]), "r"((a)[2]), "r"((a)[3]), \
          "r"((b)[0]), "r"((b)[1]))

// ---------------- prep: W bf16 hi/lo split + R transpose --------------------
__global__ void prep_w(const float* __restrict__ At, const float* __restrict__ Ac,
                       const float* __restrict__ Bc, const float* __restrict__ R)
{
    int i = blockIdx.x * 256 + threadIdx.x;  // 0..32767
    if (i < 32768) {
        const float* srcs[3] = {At, Ac, Bc};
        #pragma unroll
        for (int m = 0; m < 3; m++) {
            float a  = srcs[m][i];
            __nv_bfloat16 h = __float2bfloat16_rn(a);
            float lo = a - __bfloat162float(h);
            g_wbhi[m*32768 + i] = h;
            g_wblo[m*32768 + i] = __float2bfloat16_rn(lo);
        }
        int e = i >> 8, oo = i & 255;      // R is (128, 256)
        g_rt[oo*128 + e] = R[i];
    }
}

// ---------------- tensor-core projection via warp mma.sync ------------------
// C[128 x 128half] = X[128 x 128] * W^T, bf16 3-product split, fp32 accum.
// Block: 256 threads = 8 warps, 4(M) x 2(N); warp tile 32 x 64.
// K streamed in 4 chunks of 32. smem rows stride 40 bf16 (80B, 16B-aligned,
// 5r mod 8 -> conflict-free ldmatrix).
#define SSTR 40

template<int RPB, int DST>
__global__ __launch_bounds__(256)
void proj_mma(const float* __restrict__ X, const float* __restrict__ bias, int widx)
{
    __shared__ __nv_bfloat16 sAhi[128*SSTR];
    __shared__ __nv_bfloat16 sAlo[128*SSTR];
    __shared__ __nv_bfloat16 sBhi[128*SSTR];
    __shared__ __nv_bfloat16 sBlo[128*SSTR];

    float* __restrict__ Y = (DST == 0) ? g_qh : (DST == 1) ? g_kh : g_vp;
    const __nv_bfloat16* __restrict__ Whi = g_wbhi + widx * 32768;
    const __nv_bfloat16* __restrict__ Wlo = g_wblo + widx * 32768;

    const int tid    = threadIdx.x;
    const int wid    = tid >> 5;
    const int lane   = tid & 31;
    const int warp_m = wid & 3;        // 4 warps over M
    const int warp_n = wid >> 2;       // 2 warps over N
    const int row0   = blockIdx.x * 128;
    const int nb     = blockIdx.y * 128;

    const uint32_t bAhi = smem_u32(sAhi);
    const uint32_t bAlo = smem_u32(sAlo);
    const uint32_t bBhi = smem_u32(sBhi);
    const uint32_t bBlo = smem_u32(sBlo);

    // ldmatrix per-thread address components
    const int lr = lane & 7;
    const int lq = lane >> 3;
    // A: matrix quad -> row + 8*(q&1), col16 = q>>1
    const uint32_t aoff = (uint32_t)((warp_m*32 + lr + 8*(lq & 1)) * 80 + (lq >> 1) * 16);
    // B: matrix quad -> ntile-pair offset 8*(q>>1), col16 = q&1
    const uint32_t boff = (uint32_t)((warp_n*64 + lr + 8*(lq >> 1)) * 80 + (lq & 1) * 16);

    float acc[2][8][4];
    #pragma unroll
    for (int mt = 0; mt < 2; mt++)
        #pragma unroll
        for (int nt = 0; nt < 8; nt++)
            #pragma unroll
            for (int j = 0; j < 4; j++) acc[mt][nt][j] = 0.f;

    for (int kk = 0; kk < 4; kk++) {
        __syncthreads();   // previous chunk's reads done

        // ---- X chunk: 128 rows x 32 k, fp32 -> bf16 hi/lo in smem ----
        #pragma unroll
        for (int i = 0; i < 4; i++) {
            int idx = tid + i * 256;               // 0..1023
            int r = idx >> 3, f4 = idx & 7;        // f4: k-group of 4
            float4 x = *(const float4*)(X + (long long)(row0 + r) * EMB + kk*32 + f4*4);
            __nv_bfloat162 h01 = __floats2bfloat162_rn(x.x, x.y);
            __nv_bfloat162 h23 = __floats2bfloat162_rn(x.z, x.w);
            float l0 = x.x - __low2float(h01),  l1 = x.y - __high2float(h01);
            float l2 = x.z - __low2float(h23),  l3 = x.w - __high2float(h23);
            __nv_bfloat162 lo01 = __floats2bfloat162_rn(l0, l1);
            __nv_bfloat162 lo23 = __floats2bfloat162_rn(l2, l3);
            uint2 hv = make_uint2(*(uint32_t*)&h01, *(uint32_t*)&h23);
            uint2 lv = make_uint2(*(uint32_t*)&lo01, *(uint32_t*)&lo23);
            *(uint2*)&sAhi[r*SSTR + f4*4] = hv;
            *(uint2*)&sAlo[r*SSTR + f4*4] = lv;
        }
        // ---- W chunk: 128 o-rows x 32 k (already bf16 hi/lo) ----
        #pragma unroll
        for (int i = 0; i < 2; i++) {
            int idx = tid + i * 256;               // 0..511
            int r = idx >> 2, g = idx & 3;         // g: k-group of 8
            const long long src = (long long)(nb + r) * EMB + kk*32 + g*8;
            *(uint4*)&sBhi[r*SSTR + g*8] = *(const uint4*)&Whi[src];
            *(uint4*)&sBlo[r*SSTR + g*8] = *(const uint4*)&Wlo[src];
        }
        __syncthreads();

        #pragma unroll
        for (int ks = 0; ks < 2; ks++) {           // k-steps of 16 within chunk
            const uint32_t kb = (uint32_t)(kk & 0) + ks * 32;  // ks*16 halves = 32B
            uint32_t ahi[2][4], alo[2][4];
            #pragma unroll
            for (int mt = 0; mt < 2; mt++) {
                LDSM_X4(ahi[mt], bAhi + aoff + mt*16*80 + kb);
                LDSM_X4(alo[mt], bAlo + aoff + mt*16*80 + kb);
            }
            uint32_t bhi[16], blo[16];
            #pragma unroll
            for (int np = 0; np < 4; np++) {       // pairs of n-tiles
                LDSM_X4(&bhi[np*4], bBhi + boff + np*16*80 + kb);
                LDSM_X4(&blo[np*4], bBlo + boff + np*16*80 + kb);
            }
            #pragma unroll
            for (int mt = 0; mt < 2; mt++)
                #pragma unroll
                for (int nt = 0; nt < 8; nt++) {
                    MMA_BF16(acc[mt][nt], ahi[mt], &bhi[nt*2]);
                    MMA_BF16(acc[mt][nt], ahi[mt], &blo[nt*2]);
                    MMA_BF16(acc[mt][nt], alo[mt], &bhi[nt*2]);
                }
        }
    }

    // ---- epilogue: + bias, scatter to (b, h, seq, d) ----
    #pragma unroll
    for (int mt = 0; mt < 2; mt++) {
        const int r0 = row0 + warp_m*32 + mt*16 + (lane >> 2);
        const int r1 = r0 + 8;
        const int bb0 = r0 / RPB, cc0 = r0 - bb0 * RPB;
        const int bb1 = r1 / RPB, cc1 = r1 - bb1 * RPB;
        #pragma unroll
        for (int nt = 0; nt < 8; nt++) {
            const int o = nb + warp_n*64 + nt*8 + (lane & 3)*2;
            const int h = o >> 5, d = o & 31;
            const float2 bv = *(const float2*)&bias[o];
            float2 v0 = make_float2(acc[mt][nt][0] + bv.x, acc[mt][nt][1] + bv.y);
            float2 v1 = make_float2(acc[mt][nt][2] + bv.x, acc[mt][nt][3] + bv.y);
            *(float2*)&Y[(((long long)bb0 * NH + h) * RPB + cc0) * DK + d] = v0;
            *(float2*)&Y[(((long long)bb1 * NH + h) * RPB + cc1) * DK + d] = v1;
        }
    }
}

// ---------------- fused attention per (b,h), two 25-row t-passes -----------
#define TP 25
__global__ __launch_bounds__(256)
void att_kernel(const float* __restrict__ pos_bias,
                float* __restrict__ att_out, int write_att)
{
    __shared__ float svp[WINDOW * DK];   // 6400 floats
    __shared__ float sq [TP * DK];       // 800 floats
    __shared__ float S  [TP * WINDOW];   // 5000 floats
    __shared__ float sqs[32];            // q row scales

    const int bh = blockIdx.x;
    const int b  = bh >> 3;
    const int h  = bh & 7;

    const float* kh = g_kh + (long long)bh * WINDOW * DK;
    const float* vp = g_vp + (long long)bh * WINDOW * DK;
    const float* qh = g_qh + (long long)bh * NT * DK;

    {
        const float4* vg = (const float4*)vp;
        float4* sv4 = (float4*)svp;
        #pragma unroll
        for (int i = 0; i < 7; i++) {
            int idx = threadIdx.x + i * 256;
            if (idx < 1600) sv4[idx] = vg[idx];
        }
    }

    const int c = threadIdx.x;
    float4 kc[8];
    float pb = 0.f;
    if (c < WINDOW) {
        const float4* kg = (const float4*)(kh + c * DK);
        float ss = 0.f;
        #pragma unroll
        for (int j = 0; j < 8; j++) {
            kc[j] = kg[j];
            ss += kc[j].x*kc[j].x + kc[j].y*kc[j].y + kc[j].z*kc[j].z + kc[j].w*kc[j].w;
        }
        const float sc = rsqrtf(fmaxf(ss, 1e-24f));
        #pragma unroll
        for (int j = 0; j < 8; j++) {
            kc[j].x *= sc; kc[j].y *= sc; kc[j].z *= sc; kc[j].w *= sc;
        }
        pb = pos_bias[c];
    }

    const int warp = threadIdx.x >> 5;
    const int lane = threadIdx.x & 31;
    const int dg   = threadIdx.x & 7;
    const int trow = threadIdx.x >> 3;
    const float4* v4 = (const float4*)svp;

    #pragma unroll
    for (int pass = 0; pass < 2; pass++) {
        const int t0 = pass * TP;
        __syncthreads();
        {
            const float4* qg = (const float4*)(qh + t0 * DK);
            float4* sq4 = (float4*)sq;
            if (threadIdx.x < 200) sq4[threadIdx.x] = qg[threadIdx.x];
        }
        __syncthreads();
        if (threadIdx.x < TP) {
            const float4* r4 = (const float4*)(sq + threadIdx.x * DK);
            float ss = 0.f;
            #pragma unroll
            for (int j = 0; j < 8; j++) {
                float4 q = r4[j];
                ss += q.x*q.x + q.y*q.y + q.z*q.z + q.w*q.w;
            }
            sqs[threadIdx.x] = rsqrtf(fmaxf(ss, 1e-24f));
        }
        __syncthreads();
        if (threadIdx.x < 200) {
            float4* sq4 = (float4*)sq;
            float4 q = sq4[threadIdx.x];
            const float sc = sqs[threadIdx.x >> 3];
            q.x *= sc; q.y *= sc; q.z *= sc; q.w *= sc;
            sq4[threadIdx.x] = q;
        }
        __syncthreads();

        if (c < WINDOW) {
            for (int t = 0; t < TP; t++) {
                float2 a = make_float2(0.f, 0.f);
                const float4* q4 = (const float4*)(sq + t * DK);
                #pragma unroll
                for (int j = 0; j < 8; j++) {
                    float4 q = q4[j];
                    a = ffma2(make_float2(q.x, q.y), make_float2(kc[j].x, kc[j].y), a);
                    a = ffma2(make_float2(q.z, q.w), make_float2(kc[j].z, kc[j].w), a);
                }
                S[t * WINDOW + c] = a.x + a.y + pb;
            }
        }
        __syncthreads();

        for (int t = warp; t < TP; t += 8) {
            float v[7];
            #pragma unroll
            for (int j = 0; j < 7; j++) {
                int cc = lane + 32 * j;
                v[j] = (cc < WINDOW) ? S[t * WINDOW + cc] : -1e30f;
            }
            float mx = v[0];
            #pragma unroll
            for (int j = 1; j < 7; j++) mx = fmaxf(mx, v[j]);
            #pragma unroll
            for (int s = 16; s > 0; s >>= 1)
                mx = fmaxf(mx, __shfl_xor_sync(0xffffffffu, mx, s));
            float sum = 0.f;
            #pragma unroll
            for (int j = 0; j < 7; j++) { v[j] = __expf(v[j] - mx); sum += v[j]; }
            #pragma unroll
            for (int s = 16; s > 0; s >>= 1)
                sum += __shfl_xor_sync(0xffffffffu, sum, s);
            const float inv = 1.0f / sum;
            #pragma unroll
            for (int j = 0; j < 7; j++) {
                int cc = lane + 32 * j;
                if (cc < WINDOW) {
                    float a = v[j] * inv;
                    S[t * WINDOW + cc] = a;
                    if (write_att)
                        att_out[((long long)bh * NT + (t0 + t)) * WINDOW + cc] = a;
                }
            }
        }
        __syncthreads();

        if (trow < TP) {
            const int t = trow;
            float2 axy = make_float2(0.f, 0.f), azw = make_float2(0.f, 0.f);
            const float* Srow = S + t * WINDOW;
            for (int c0 = 0; c0 < WINDOW; c0 += 2) {
                float2 s2 = *(const float2*)(Srow + c0);
                float4 v0 = v4[(c0    ) * 8 + dg];
                float4 v1 = v4[(c0 + 1) * 8 + dg];
                axy = ffma2(make_float2(s2.x, s2.x), make_float2(v0.x, v0.y), axy);
                azw = ffma2(make_float2(s2.x, s2.x), make_float2(v0.z, v0.w), azw);
                axy = ffma2(make_float2(s2.y, s2.y), make_float2(v1.x, v1.y), axy);
                azw = ffma2(make_float2(s2.y, s2.y), make_float2(v1.z, v1.w), azw);
            }
            float4 o4 = make_float4(axy.x, axy.y, azw.x, azw.y);
            *(float4*)(g_oh + ((long long)b * NT + (t0 + t)) * (NH * DK) + h * DK + dg * 4) = o4;
        }
    }
}

// ---------------- final projection: out = oh @ R^T + Rb --------------------
__global__ __launch_bounds__(256)
void out_kernel(const float* __restrict__ Rb, float* __restrict__ out)
{
    __shared__ float sx[25 * 256];
    __shared__ float pbuf[25 * 128];
    const int row0 = blockIdx.x * 25;

    const float4* xg = (const float4*)(g_oh + (long long)row0 * 256);
    float4* sx4 = (float4*)sx;
    #pragma unroll
    for (int i = 0; i < 7; i++) {
        int idx = threadIdx.x + i * 256;
        if (idx < 1600) sx4[idx] = xg[idx];
    }
    __syncthreads();

    const int e    = threadIdx.x & 127;
    const int half = threadIdx.x >> 7;
    float2 acc[25];
    #pragma unroll
    for (int r = 0; r < 25; r++) acc[r] = make_float2(0.f, 0.f);

    const int k0 = half * 128;
    for (int k = 0; k < 128; k += 4) {
        const int kk = k0 + k;
        float w0 = g_rt[(kk+0)*128 + e];
        float w1 = g_rt[(kk+1)*128 + e];
        float w2 = g_rt[(kk+2)*128 + e];
        float w3 = g_rt[(kk+3)*128 + e];
        float2 wab = make_float2(w0, w1), wcd = make_float2(w2, w3);
        #pragma unroll
        for (int r = 0; r < 25; r++) {
            float4 x4 = *(const float4*)&sx[r*256 + kk];
            acc[r] = ffma2(make_float2(x4.x, x4.y), wab, acc[r]);
            acc[r] = ffma2(make_float2(x4.z, x4.w), wcd, acc[r]);
        }
    }

    if (half == 1) {
        #pragma unroll
        for (int r = 0; r < 25; r++) pbuf[r*128 + e] = acc[r].x + acc[r].y;
    }
    __syncthreads();
    if (half == 0) {
        const float bo = Rb[e];
        #pragma unroll
        for (int r = 0; r < 25; r++) {
            out[(long long)(row0 + r) * 128 + e] =
                acc[r].x + acc[r].y + pbuf[r*128 + e] + bo;
        }
    }
}

// ---------------- launch: kernel launches ONLY (graph-capture safe) --------
extern "C" void kernel_launch(void* const* d_in, const int* in_sizes, int n_in,
                              void* d_out, int out_size)
{
    const float* queries  = (const float*)d_in[0];
    const float* keys     = (const float*)d_in[1];
    const float* values   = (const float*)d_in[2];
    const float* At_w     = (const float*)d_in[3];
    const float* At_b     = (const float*)d_in[4];
    const float* Ac_w     = (const float*)d_in[5];
    const float* Ac_b     = (const float*)d_in[6];
    const float* Bc_w     = (const float*)d_in[7];
    const float* Bc_b     = (const float*)d_in[8];
    const float* pos_bias = (const float*)d_in[9];
    const float* R_w      = (const float*)d_in[10];
    const float* R_b      = (const float*)d_in[11];
    float* out = (float*)d_out;

    prep_w<<<128, 256>>>(At_w, Ac_w, Bc_w, R_w);

    proj_mma<NT,     0><<<dim3(NB*NT/128,     2), 256>>>(queries, At_b, 0);
    proj_mma<WINDOW, 1><<<dim3(NB*WINDOW/128, 2), 256>>>(keys,    Ac_b, 1);
    proj_mma<WINDOW, 2><<<dim3(NB*WINDOW/128, 2), 256>>>(values,  Bc_b, 2);

    const long long need = (long long)OUT_ELEMS + (long long)ATT_ELEMS;
    const int write_att = ((long long)out_size >= need) ? 1 : 0;
    att_kernel<<<NB*NH, 256>>>(pos_bias, out + OUT_ELEMS, write_att);

    out_kernel<<<NB*NT/25, 256>>>(R_b, out);
}

// round 8
// speedup vs baseline: 1.4976x; 1.0289x over previous
#include <cuda_runtime.h>
#include <cuda_bf16.h>
#include <math.h>
#include <stdint.h>

#define EMB 128
#define WINDOW 200
#define DK 32
#define NH 8
#define NT 50
#define NB 1024

#define OUT_ELEMS (NB*NT*EMB)          // 6,553,600
#define ATT_ELEMS (NB*NH*NT*WINDOW)    // 81,920,000

// ---------------- scratch (device globals; no runtime allocation) ----------
__device__ float g_qh[NB*NH*NT*DK];       // q projection  (b,h,t,d)
__device__ float g_kh[NB*NH*WINDOW*DK];   // k projection  (b,h,c,d)
__device__ float g_vp[NB*NH*WINDOW*DK];   // v projection  (b,h,c,d)
__device__ float g_oh[NB*NT*NH*DK];       // out heads     (b,t,h*32+d)
__device__ float g_rt [256*EMB];          // R_w transposed:  [o][e]
__device__ __nv_bfloat16 g_wbhi[3*256*EMB];  // W hi bf16, [o][k] k-major
__device__ __nv_bfloat16 g_wblo[3*256*EMB];  // W lo residual bf16

// ================= helpers ==================================================
__device__ __forceinline__ uint32_t smem_u32(const void* p) {
    uint32_t a;
    asm("{ .reg .u64 t; cvta.to.shared.u64 t, %1; cvt.u32.u64 %0, t; }"
        : "=r"(a) : "l"(p));
    return a;
}

// packed f32x2 FMA (for att / out kernels)
__device__ __forceinline__ float2 ffma2(float2 a, float2 b, float2 c) {
    unsigned long long au, bu, cu, du;
    asm("mov.b64 %0, {%1, %2};" : "=l"(au) : "f"(a.x), "f"(a.y));
    asm("mov.b64 %0, {%1, %2};" : "=l"(bu) : "f"(b.x), "f"(b.y));
    asm("mov.b64 %0, {%1, %2};" : "=l"(cu) : "f"(c.x), "f"(c.y));
    asm("fma.rn.f32x2 %0, %1, %2, %3;" : "=l"(du) : "l"(au), "l"(bu), "l"(cu));
    float2 r;
    asm("mov.b64 {%0, %1}, %2;" : "=f"(r.x), "=f"(r.y) : "l"(du));
    return r;
}

#define LDSM_X4(d, addr) \
    asm volatile("ldmatrix.sync.aligned.m8n8.x4.shared.b16 {%0,%1,%2,%3}, [%4];" \
        : "=r"((d)[0]), "=r"((d)[1]), "=r"((d)[2]), "=r"((d)[3]) : "r"(addr))

#define MMA_BF16(c, a, b) \
    asm volatile("mma.sync.aligned.m16n8k16.row.col.f32.bf16.bf16.f32 " \
        "{%0,%1,%2,%3}, {%4,%5,%6,%7}, {%8,%9}, {%0,%1,%2,%3};" \
        : "+f"((c)[0]), "+f"((c)[1]), "+f"((c)[2]), "+f"((c)[3]) \
        : "r"((a)[0]), "r"((a)[1]), "r"((a)[2]), "r"((a)[3]), \
          "r"((b)[0]), "r"((b)[1]))

#define CP_ASYNC16(dst_u32, src_ptr) \
    asm volatile("cp.async.cg.shared.global [%0], [%1], 16;" \
                 :: "r"(dst_u32), "l"(src_ptr) : "memory")
#define CP_COMMIT() asm volatile("cp.async.commit_group;" ::: "memory")
#define CP_WAIT0()  asm volatile("cp.async.wait_group 0;" ::: "memory")

// ---------------- prep: W bf16 hi/lo split + R transpose --------------------
__global__ void prep_w(const float* __restrict__ At, const float* __restrict__ Ac,
                       const float* __restrict__ Bc, const float* __restrict__ R)
{
    int i = blockIdx.x * 256 + threadIdx.x;  // 0..32767
    if (i < 32768) {
        const float* srcs[3] = {At, Ac, Bc};
        #pragma unroll
        for (int m = 0; m < 3; m++) {
            float a  = srcs[m][i];
            __nv_bfloat16 h = __float2bfloat16_rn(a);
            float lo = a - __bfloat162float(h);
            g_wbhi[m*32768 + i] = h;
            g_wblo[m*32768 + i] = __float2bfloat16_rn(lo);
        }
        int e = i >> 8, oo = i & 255;      // R is (128, 256)
        g_rt[oo*128 + e] = R[i];
    }
}

// ---------------- proj pipeline helpers (free functions, no lambdas) --------
#define SSTR 40

__device__ __forceinline__ void proj_load(
    const float* __restrict__ X, const __nv_bfloat16* __restrict__ Whi,
    const __nv_bfloat16* __restrict__ Wlo, int row0, int nb, int kk, int tid,
    float4* xv, uint4* bhv, uint4* blv)
{
    #pragma unroll
    for (int i = 0; i < 4; i++) {
        int idx = tid + i * 256;
        int r = idx >> 3, f4 = idx & 7;
        xv[i] = *(const float4*)(X + (long long)(row0 + r) * EMB + kk*32 + f4*4);
    }
    #pragma unroll
    for (int i = 0; i < 2; i++) {
        int idx = tid + i * 256;
        int r = idx >> 2, g = idx & 3;
        const long long src = (long long)(nb + r) * EMB + kk*32 + g*8;
        bhv[i] = *(const uint4*)&Whi[src];
        blv[i] = *(const uint4*)&Wlo[src];
    }
}

__device__ __forceinline__ void proj_store(
    __nv_bfloat16* sAhi, __nv_bfloat16* sAlo,
    __nv_bfloat16* sBhi, __nv_bfloat16* sBlo, int tid,
    const float4* xv, const uint4* bhv, const uint4* blv)
{
    #pragma unroll
    for (int i = 0; i < 4; i++) {
        int idx = tid + i * 256;
        int r = idx >> 3, f4 = idx & 7;
        float4 x = xv[i];
        __nv_bfloat162 h01 = __floats2bfloat162_rn(x.x, x.y);
        __nv_bfloat162 h23 = __floats2bfloat162_rn(x.z, x.w);
        float l0 = x.x - __low2float(h01),  l1 = x.y - __high2float(h01);
        float l2 = x.z - __low2float(h23),  l3 = x.w - __high2float(h23);
        __nv_bfloat162 lo01 = __floats2bfloat162_rn(l0, l1);
        __nv_bfloat162 lo23 = __floats2bfloat162_rn(l2, l3);
        uint32_t h01u, h23u, lo01u, lo23u;
        memcpy(&h01u, &h01, 4);  memcpy(&h23u, &h23, 4);
        memcpy(&lo01u, &lo01, 4); memcpy(&lo23u, &lo23, 4);
        *(uint2*)&sAhi[r*SSTR + f4*4] = make_uint2(h01u, h23u);
        *(uint2*)&sAlo[r*SSTR + f4*4] = make_uint2(lo01u, lo23u);
    }
    #pragma unroll
    for (int i = 0; i < 2; i++) {
        int idx = tid + i * 256;
        int r = idx >> 2, g = idx & 3;
        *(uint4*)&sBhi[r*SSTR + g*8] = bhv[i];
        *(uint4*)&sBlo[r*SSTR + g*8] = blv[i];
    }
}

// ---------------- tensor-core projection via warp mma.sync ------------------
// C[128 x 128half] = X[128 x 128] * W^T, bf16 3-product split, fp32 accum.
// Block: 256 threads = 8 warps, 4(M) x 2(N); warp tile 32 x 64.
// K in 4 chunks of 32, software-pipelined: chunk k+1 LDG'd into registers
// before the MMA phase of chunk k.
template<int RPB, int DST>
__global__ __launch_bounds__(256)
void proj_mma(const float* __restrict__ X, const float* __restrict__ bias, int widx)
{
    __shared__ __nv_bfloat16 sAhi[128*SSTR];
    __shared__ __nv_bfloat16 sAlo[128*SSTR];
    __shared__ __nv_bfloat16 sBhi[128*SSTR];
    __shared__ __nv_bfloat16 sBlo[128*SSTR];

    float* __restrict__ Y = (DST == 0) ? g_qh : (DST == 1) ? g_kh : g_vp;
    const __nv_bfloat16* __restrict__ Whi = g_wbhi + widx * 32768;
    const __nv_bfloat16* __restrict__ Wlo = g_wblo + widx * 32768;

    const int tid    = threadIdx.x;
    const int wid    = tid >> 5;
    const int lane   = tid & 31;
    const int warp_m = wid & 3;
    const int warp_n = wid >> 2;
    const int row0   = blockIdx.x * 128;
    const int nb     = blockIdx.y * 128;

    const uint32_t bAhi = smem_u32(sAhi);
    const uint32_t bAlo = smem_u32(sAlo);
    const uint32_t bBhi = smem_u32(sBhi);
    const uint32_t bBlo = smem_u32(sBlo);

    const int lr = lane & 7;
    const int lq = lane >> 3;
    const uint32_t aoff = (uint32_t)((warp_m*32 + lr + 8*(lq & 1)) * 80 + (lq >> 1) * 16);
    const uint32_t boff = (uint32_t)((warp_n*64 + lr + 8*(lq >> 1)) * 80 + (lq & 1) * 16);

    float4 xv[4];
    uint4  bhv[2], blv[2];

    float acc[2][8][4];
    #pragma unroll
    for (int mt = 0; mt < 2; mt++)
        #pragma unroll
        for (int nt = 0; nt < 8; nt++)
            #pragma unroll
            for (int j = 0; j < 4; j++) acc[mt][nt][j] = 0.f;

    proj_load(X, Whi, Wlo, row0, nb, 0, tid, xv, bhv, blv);

    for (int kk = 0; kk < 4; kk++) {
        if (kk) __syncthreads();   // consumers of chunk kk-1 done with smem
        proj_store(sAhi, sAlo, sBhi, sBlo, tid, xv, bhv, blv);
        __syncthreads();
        if (kk < 3)                // LDGs fly during MMA phase
            proj_load(X, Whi, Wlo, row0, nb, kk + 1, tid, xv, bhv, blv);

        #pragma unroll
        for (int ks = 0; ks < 2; ks++) {
            const uint32_t kb = ks * 32;
            uint32_t ahi[2][4], alo[2][4];
            #pragma unroll
            for (int mt = 0; mt < 2; mt++) {
                LDSM_X4(ahi[mt], bAhi + aoff + mt*16*80 + kb);
                LDSM_X4(alo[mt], bAlo + aoff + mt*16*80 + kb);
            }
            uint32_t bhi[16], blo[16];
            #pragma unroll
            for (int np = 0; np < 4; np++) {
                LDSM_X4(&bhi[np*4], bBhi + boff + np*16*80 + kb);
                LDSM_X4(&blo[np*4], bBlo + boff + np*16*80 + kb);
            }
            #pragma unroll
            for (int mt = 0; mt < 2; mt++)
                #pragma unroll
                for (int nt = 0; nt < 8; nt++) {
                    MMA_BF16(acc[mt][nt], ahi[mt], &bhi[nt*2]);
                    MMA_BF16(acc[mt][nt], ahi[mt], &blo[nt*2]);
                    MMA_BF16(acc[mt][nt], alo[mt], &bhi[nt*2]);
                }
        }
    }

    // ---- epilogue: + bias, scatter to (b, h, seq, d) ----
    #pragma unroll
    for (int mt = 0; mt < 2; mt++) {
        const int r0 = row0 + warp_m*32 + mt*16 + (lane >> 2);
        const int r1 = r0 + 8;
        const int bb0 = r0 / RPB, cc0 = r0 - bb0 * RPB;
        const int bb1 = r1 / RPB, cc1 = r1 - bb1 * RPB;
        #pragma unroll
        for (int nt = 0; nt < 8; nt++) {
            const int o = nb + warp_n*64 + nt*8 + (lane & 3)*2;
            const int h = o >> 5, d = o & 31;
            const float2 bv = *(const float2*)&bias[o];
            float2 v0 = make_float2(acc[mt][nt][0] + bv.x, acc[mt][nt][1] + bv.y);
            float2 v1 = make_float2(acc[mt][nt][2] + bv.x, acc[mt][nt][3] + bv.y);
            *(float2*)&Y[(((long long)bb0 * NH + h) * RPB + cc0) * DK + d] = v0;
            *(float2*)&Y[(((long long)bb1 * NH + h) * RPB + cc1) * DK + d] = v1;
        }
    }
}

// ---------------- fused attention per (b,h), two 25-row t-passes -----------
// v via cp.async (waited before first AV use); q normalize fused into load
// (one thread per q row). 3 syncs per pass.
#define TP 25
__global__ __launch_bounds__(256)
void att_kernel(const float* __restrict__ pos_bias,
                float* __restrict__ att_out, int write_att)
{
    __shared__ float svp[WINDOW * DK];   // 6400 floats
    __shared__ float sq [TP * DK];       // 800 floats
    __shared__ float S  [TP * WINDOW];   // 5000 floats

    const int bh = blockIdx.x;
    const int b  = bh >> 3;
    const int h  = bh & 7;

    const float* kh = g_kh + (long long)bh * WINDOW * DK;
    const float* vp = g_vp + (long long)bh * WINDOW * DK;
    const float* qh = g_qh + (long long)bh * NT * DK;

    // v tile: async copy, completion needed only at first AV phase
    {
        const uint32_t sv = smem_u32(svp);
        #pragma unroll
        for (int i = 0; i < 7; i++) {
            int idx = threadIdx.x + i * 256;
            if (idx < 1600) CP_ASYNC16(sv + idx * 16, (const float4*)vp + idx);
        }
        CP_COMMIT();
    }

    // k row for this thread: load + normalize in registers
    const int c = threadIdx.x;
    float4 kc[8];
    float pb = 0.f;
    if (c < WINDOW) {
        const float4* kg = (const float4*)(kh + c * DK);
        float ss = 0.f;
        #pragma unroll
        for (int j = 0; j < 8; j++) {
            kc[j] = kg[j];
            ss += kc[j].x*kc[j].x + kc[j].y*kc[j].y + kc[j].z*kc[j].z + kc[j].w*kc[j].w;
        }
        const float sc = rsqrtf(fmaxf(ss, 1e-24f));
        #pragma unroll
        for (int j = 0; j < 8; j++) {
            kc[j].x *= sc; kc[j].y *= sc; kc[j].z *= sc; kc[j].w *= sc;
        }
        pb = pos_bias[c];
    }

    const int warp = threadIdx.x >> 5;
    const int lane = threadIdx.x & 31;
    const int dg   = threadIdx.x & 7;
    const int trow = threadIdx.x >> 3;
    const float4* v4 = (const float4*)svp;

    for (int pass = 0; pass < 2; pass++) {
        const int t0 = pass * TP;

        // q rows: one thread per row, LDG -> normalize -> STS
        if (threadIdx.x < TP) {
            const float4* qg = (const float4*)(qh + (t0 + threadIdx.x) * DK);
            float4 qr[8];
            float ss = 0.f;
            #pragma unroll
            for (int j = 0; j < 8; j++) {
                qr[j] = qg[j];
                ss += qr[j].x*qr[j].x + qr[j].y*qr[j].y + qr[j].z*qr[j].z + qr[j].w*qr[j].w;
            }
            const float sc = rsqrtf(fmaxf(ss, 1e-24f));
            float4* sq4 = (float4*)(sq + threadIdx.x * DK);
            #pragma unroll
            for (int j = 0; j < 8; j++) {
                float4 q = qr[j];
                q.x *= sc; q.y *= sc; q.z *= sc; q.w *= sc;
                sq4[j] = q;
            }
        }
        __syncthreads();   // sq ready; prior pass fully done with S

        // ---- scores: S[t][c] = qhat(t)·khat(c) + pos_bias[c] ----
        if (c < WINDOW) {
            for (int t = 0; t < TP; t++) {
                float2 a = make_float2(0.f, 0.f);
                const float4* q4 = (const float4*)(sq + t * DK);
                #pragma unroll
                for (int j = 0; j < 8; j++) {
                    float4 q = q4[j];
                    a = ffma2(make_float2(q.x, q.y), make_float2(kc[j].x, kc[j].y), a);
                    a = ffma2(make_float2(q.z, q.w), make_float2(kc[j].z, kc[j].w), a);
                }
                S[t * WINDOW + c] = a.x + a.y + pb;
            }
        }
        __syncthreads();

        // ---- softmax: one warp per row; att written straight to gmem ----
        for (int t = warp; t < TP; t += 8) {
            float v[7];
            #pragma unroll
            for (int j = 0; j < 7; j++) {
                int cc = lane + 32 * j;
                v[j] = (cc < WINDOW) ? S[t * WINDOW + cc] : -1e30f;
            }
            float mx = v[0];
            #pragma unroll
            for (int j = 1; j < 7; j++) mx = fmaxf(mx, v[j]);
            #pragma unroll
            for (int s = 16; s > 0; s >>= 1)
                mx = fmaxf(mx, __shfl_xor_sync(0xffffffffu, mx, s));
            float sum = 0.f;
            #pragma unroll
            for (int j = 0; j < 7; j++) { v[j] = __expf(v[j] - mx); sum += v[j]; }
            #pragma unroll
            for (int s = 16; s > 0; s >>= 1)
                sum += __shfl_xor_sync(0xffffffffu, sum, s);
            const float inv = 1.0f / sum;
            #pragma unroll
            for (int j = 0; j < 7; j++) {
                int cc = lane + 32 * j;
                if (cc < WINDOW) {
                    float a = v[j] * inv;
                    S[t * WINDOW + cc] = a;
                    if (write_att)
                        att_out[((long long)bh * NT + (t0 + t)) * WINDOW + cc] = a;
                }
            }
        }
        if (pass == 0) CP_WAIT0();   // v must be resident before first AV
        __syncthreads();

        // ---- out_heads[t][d] = sum_c att[t][c] * v[c][d] ----
        if (trow < TP) {
            const int t = trow;
            float2 axy = make_float2(0.f, 0.f), azw = make_float2(0.f, 0.f);
            const float* Srow = S + t * WINDOW;
            for (int c0 = 0; c0 < WINDOW; c0 += 2) {
                float2 s2 = *(const float2*)(Srow + c0);
                float4 v0 = v4[(c0    ) * 8 + dg];
                float4 v1 = v4[(c0 + 1) * 8 + dg];
                axy = ffma2(make_float2(s2.x, s2.x), make_float2(v0.x, v0.y), axy);
                azw = ffma2(make_float2(s2.x, s2.x), make_float2(v0.z, v0.w), azw);
                axy = ffma2(make_float2(s2.y, s2.y), make_float2(v1.x, v1.y), axy);
                azw = ffma2(make_float2(s2.y, s2.y), make_float2(v1.z, v1.w), azw);
            }
            float4 o4 = make_float4(axy.x, axy.y, azw.x, azw.y);
            *(float4*)(g_oh + ((long long)b * NT + (t0 + t)) * (NH * DK) + h * DK + dg * 4) = o4;
        }
    }
}

// ---------------- final projection: out = oh @ R^T + Rb --------------------
__global__ __launch_bounds__(256)
void out_kernel(const float* __restrict__ Rb, float* __restrict__ out)
{
    __shared__ float sx[25 * 256];
    __shared__ float pbuf[25 * 128];
    const int row0 = blockIdx.x * 25;

    const float4* xg = (const float4*)(g_oh + (long long)row0 * 256);
    float4* sx4 = (float4*)sx;
    #pragma unroll
    for (int i = 0; i < 7; i++) {
        int idx = threadIdx.x + i * 256;
        if (idx < 1600) sx4[idx] = xg[idx];
    }
    __syncthreads();

    const int e    = threadIdx.x & 127;
    const int half = threadIdx.x >> 7;
    float2 acc[25];
    #pragma unroll
    for (int r = 0; r < 25; r++) acc[r] = make_float2(0.f, 0.f);

    const int k0 = half * 128;
    for (int k = 0; k < 128; k += 4) {
        const int kk = k0 + k;
        float w0 = g_rt[(kk+0)*128 + e];
        float w1 = g_rt[(kk+1)*128 + e];
        float w2 = g_rt[(kk+2)*128 + e];
        float w3 = g_rt[(kk+3)*128 + e];
        float2 wab = make_float2(w0, w1), wcd = make_float2(w2, w3);
        #pragma unroll
        for (int r = 0; r < 25; r++) {
            float4 x4 = *(const float4*)&sx[r*256 + kk];
            acc[r] = ffma2(make_float2(x4.x, x4.y), wab, acc[r]);
            acc[r] = ffma2(make_float2(x4.z, x4.w), wcd, acc[r]);
        }
    }

    if (half == 1) {
        #pragma unroll
        for (int r = 0; r < 25; r++) pbuf[r*128 + e] = acc[r].x + acc[r].y;
    }
    __syncthreads();
    if (half == 0) {
        const float bo = Rb[e];
        #pragma unroll
        for (int r = 0; r < 25; r++) {
            out[(long long)(row0 + r) * 128 + e] =
                acc[r].x + acc[r].y + pbuf[r*128 + e] + bo;
        }
    }
}

// ---------------- launch: kernel launches ONLY (graph-capture safe) --------
extern "C" void kernel_launch(void* const* d_in, const int* in_sizes, int n_in,
                              void* d_out, int out_size)
{
    const float* queries  = (const float*)d_in[0];
    const float* keys     = (const float*)d_in[1];
    const float* values   = (const float*)d_in[2];
    const float* At_w     = (const float*)d_in[3];
    const float* At_b     = (const float*)d_in[4];
    const float* Ac_w     = (const float*)d_in[5];
    const float* Ac_b     = (const float*)d_in[6];
    const float* Bc_w     = (const float*)d_in[7];
    const float* Bc_b     = (const float*)d_in[8];
    const float* pos_bias = (const float*)d_in[9];
    const float* R_w      = (const float*)d_in[10];
    const float* R_b      = (const float*)d_in[11];
    float* out = (float*)d_out;

    prep_w<<<128, 256>>>(At_w, Ac_w, Bc_w, R_w);

    proj_mma<NT,     0><<<dim3(NB*NT/128,     2), 256>>>(queries, At_b, 0);
    proj_mma<WINDOW, 1><<<dim3(NB*WINDOW/128, 2), 256>>>(keys,    Ac_b, 1);
    proj_mma<WINDOW, 2><<<dim3(NB*WINDOW/128, 2), 256>>>(values,  Bc_b, 2);

    const long long need = (long long)OUT_ELEMS + (long long)ATT_ELEMS;
    const int write_att = ((long long)out_size >= need) ? 1 : 0;
    att_kernel<<<NB*NH, 256>>>(pos_bias, out + OUT_ELEMS, write_att);

    out_kernel<<<NB*NT/25, 256>>>(R_b, out);
}

// round 9
// speedup vs baseline: 2.2167x; 1.4801x over previous
#include <cuda_runtime.h>
#include <cuda_bf16.h>
#include <math.h>
#include <stdint.h>

#define EMB 128
#define WINDOW 200
#define DK 32
#define NH 8
#define NT 50
#define NB 1024

#define OUT_ELEMS (NB*NT*EMB)          // 6,553,600
#define ATT_ELEMS (NB*NH*NT*WINDOW)    // 81,920,000

// ---------------- scratch (device globals; no runtime allocation) ----------
__device__ float g_qh[NB*NH*NT*DK];       // q projection  (b,h,t,d)
__device__ float g_kh[NB*NH*WINDOW*DK];   // k projection  (b,h,c,d)
__device__ float g_vp[NB*NH*WINDOW*DK];   // v projection  (b,h,c,d)
__device__ float g_oh[NB*NT*NH*DK];       // out heads     (b,t,h*32+d)
__device__ float g_rt [256*EMB];          // R_w transposed:  [o][e]
__device__ __nv_bfloat16 g_wbhi[3*256*EMB];  // W hi bf16, [o][k] k-major
__device__ __nv_bfloat16 g_wblo[3*256*EMB];  // W lo residual bf16

// ================= helpers ==================================================
__device__ __forceinline__ uint32_t smem_u32(const void* p) {
    uint32_t a;
    asm("{ .reg .u64 t; cvta.to.shared.u64 t, %1; cvt.u32.u64 %0, t; }"
        : "=r"(a) : "l"(p));
    return a;
}

__device__ __forceinline__ float2 ffma2(float2 a, float2 b, float2 c) {
    unsigned long long au, bu, cu, du;
    asm("mov.b64 %0, {%1, %2};" : "=l"(au) : "f"(a.x), "f"(a.y));
    asm("mov.b64 %0, {%1, %2};" : "=l"(bu) : "f"(b.x), "f"(b.y));
    asm("mov.b64 %0, {%1, %2};" : "=l"(cu) : "f"(c.x), "f"(c.y));
    asm("fma.rn.f32x2 %0, %1, %2, %3;" : "=l"(du) : "l"(au), "l"(bu), "l"(cu));
    float2 r;
    asm("mov.b64 {%0, %1}, %2;" : "=f"(r.x), "=f"(r.y) : "l"(du));
    return r;
}

#define LDSM_X4(d, addr) \
    asm volatile("ldmatrix.sync.aligned.m8n8.x4.shared.b16 {%0,%1,%2,%3}, [%4];" \
        : "=r"((d)[0]), "=r"((d)[1]), "=r"((d)[2]), "=r"((d)[3]) : "r"(addr))

#define LDSM_X4_T(d, addr) \
    asm volatile("ldmatrix.sync.aligned.m8n8.x4.trans.shared.b16 {%0,%1,%2,%3}, [%4];" \
        : "=r"((d)[0]), "=r"((d)[1]), "=r"((d)[2]), "=r"((d)[3]) : "r"(addr))

#define MMA_BF16(c, a, b) \
    asm volatile("mma.sync.aligned.m16n8k16.row.col.f32.bf16.bf16.f32 " \
        "{%0,%1,%2,%3}, {%4,%5,%6,%7}, {%8,%9}, {%0,%1,%2,%3};" \
        : "+f"((c)[0]), "+f"((c)[1]), "+f"((c)[2]), "+f"((c)[3]) \
        : "r"((a)[0]), "r"((a)[1]), "r"((a)[2]), "r"((a)[3]), \
          "r"((b)[0]), "r"((b)[1]))

// fp32 pair -> bf16x2 hi + bf16x2 lo residual
__device__ __forceinline__ void pack_hilo(float x0, float x1,
                                          uint32_t& hi, uint32_t& lo) {
    __nv_bfloat162 h = __floats2bfloat162_rn(x0, x1);
    float r0 = x0 - __low2float(h), r1 = x1 - __high2float(h);
    __nv_bfloat162 l = __floats2bfloat162_rn(r0, r1);
    uint32_t hu, lu;
    memcpy(&hu, &h, 4); memcpy(&lu, &l, 4);
    hi = hu; lo = lu;
}

// ---------------- prep: W bf16 hi/lo split + R transpose --------------------
__global__ void prep_w(const float* __restrict__ At, const float* __restrict__ Ac,
                       const float* __restrict__ Bc, const float* __restrict__ R)
{
    int i = blockIdx.x * 256 + threadIdx.x;
    if (i < 32768) {
        const float* srcs[3] = {At, Ac, Bc};
        #pragma unroll
        for (int m = 0; m < 3; m++) {
            float a  = srcs[m][i];
            __nv_bfloat16 h = __float2bfloat16_rn(a);
            float lo = a - __bfloat162float(h);
            g_wbhi[m*32768 + i] = h;
            g_wblo[m*32768 + i] = __float2bfloat16_rn(lo);
        }
        int e = i >> 8, oo = i & 255;
        g_rt[oo*128 + e] = R[i];
    }
}

// ---------------- proj pipeline helpers -------------------------------------
#define SSTR 40

__device__ __forceinline__ void proj_load(
    const float* __restrict__ X, const __nv_bfloat16* __restrict__ Whi,
    const __nv_bfloat16* __restrict__ Wlo, int row0, int nb, int kk, int tid,
    float4* xv, uint4* bhv, uint4* blv)
{
    #pragma unroll
    for (int i = 0; i < 4; i++) {
        int idx = tid + i * 256;
        int r = idx >> 3, f4 = idx & 7;
        xv[i] = *(const float4*)(X + (long long)(row0 + r) * EMB + kk*32 + f4*4);
    }
    #pragma unroll
    for (int i = 0; i < 2; i++) {
        int idx = tid + i * 256;
        int r = idx >> 2, g = idx & 3;
        const long long src = (long long)(nb + r) * EMB + kk*32 + g*8;
        bhv[i] = *(const uint4*)&Whi[src];
        blv[i] = *(const uint4*)&Wlo[src];
    }
}

__device__ __forceinline__ void proj_store(
    __nv_bfloat16* sAhi, __nv_bfloat16* sAlo,
    __nv_bfloat16* sBhi, __nv_bfloat16* sBlo, int tid,
    const float4* xv, const uint4* bhv, const uint4* blv)
{
    #pragma unroll
    for (int i = 0; i < 4; i++) {
        int idx = tid + i * 256;
        int r = idx >> 3, f4 = idx & 7;
        float4 x = xv[i];
        uint32_t h0, l0, h1, l1;
        pack_hilo(x.x, x.y, h0, l0);
        pack_hilo(x.z, x.w, h1, l1);
        *(uint2*)&sAhi[r*SSTR + f4*4] = make_uint2(h0, h1);
        *(uint2*)&sAlo[r*SSTR + f4*4] = make_uint2(l0, l1);
    }
    #pragma unroll
    for (int i = 0; i < 2; i++) {
        int idx = tid + i * 256;
        int r = idx >> 2, g = idx & 3;
        *(uint4*)&sBhi[r*SSTR + g*8] = bhv[i];
        *(uint4*)&sBlo[r*SSTR + g*8] = blv[i];
    }
}

// ---------------- tensor-core projection ------------------------------------
template<int RPB, int DST>
__global__ __launch_bounds__(256)
void proj_mma(const float* __restrict__ X, const float* __restrict__ bias, int widx)
{
    __shared__ __nv_bfloat16 sAhi[128*SSTR];
    __shared__ __nv_bfloat16 sAlo[128*SSTR];
    __shared__ __nv_bfloat16 sBhi[128*SSTR];
    __shared__ __nv_bfloat16 sBlo[128*SSTR];

    float* __restrict__ Y = (DST == 0) ? g_qh : (DST == 1) ? g_kh : g_vp;
    const __nv_bfloat16* __restrict__ Whi = g_wbhi + widx * 32768;
    const __nv_bfloat16* __restrict__ Wlo = g_wblo + widx * 32768;

    const int tid    = threadIdx.x;
    const int wid    = tid >> 5;
    const int lane   = tid & 31;
    const int warp_m = wid & 3;
    const int warp_n = wid >> 2;
    const int row0   = blockIdx.x * 128;
    const int nb     = blockIdx.y * 128;

    const uint32_t bAhi = smem_u32(sAhi);
    const uint32_t bAlo = smem_u32(sAlo);
    const uint32_t bBhi = smem_u32(sBhi);
    const uint32_t bBlo = smem_u32(sBlo);

    const int lr = lane & 7;
    const int lq = lane >> 3;
    const uint32_t aoff = (uint32_t)((warp_m*32 + lr + 8*(lq & 1)) * 80 + (lq >> 1) * 16);
    const uint32_t boff = (uint32_t)((warp_n*64 + lr + 8*(lq >> 1)) * 80 + (lq & 1) * 16);

    float4 xv[4];
    uint4  bhv[2], blv[2];

    float acc[2][8][4];
    #pragma unroll
    for (int mt = 0; mt < 2; mt++)
        #pragma unroll
        for (int nt = 0; nt < 8; nt++)
            #pragma unroll
            for (int j = 0; j < 4; j++) acc[mt][nt][j] = 0.f;

    proj_load(X, Whi, Wlo, row0, nb, 0, tid, xv, bhv, blv);

    for (int kk = 0; kk < 4; kk++) {
        if (kk) __syncthreads();
        proj_store(sAhi, sAlo, sBhi, sBlo, tid, xv, bhv, blv);
        __syncthreads();
        if (kk < 3)
            proj_load(X, Whi, Wlo, row0, nb, kk + 1, tid, xv, bhv, blv);

        #pragma unroll
        for (int ks = 0; ks < 2; ks++) {
            const uint32_t kb = ks * 32;
            uint32_t ahi[2][4], alo[2][4];
            #pragma unroll
            for (int mt = 0; mt < 2; mt++) {
                LDSM_X4(ahi[mt], bAhi + aoff + mt*16*80 + kb);
                LDSM_X4(alo[mt], bAlo + aoff + mt*16*80 + kb);
            }
            uint32_t bhi[16], blo[16];
            #pragma unroll
            for (int np = 0; np < 4; np++) {
                LDSM_X4(&bhi[np*4], bBhi + boff + np*16*80 + kb);
                LDSM_X4(&blo[np*4], bBlo + boff + np*16*80 + kb);
            }
            #pragma unroll
            for (int mt = 0; mt < 2; mt++)
                #pragma unroll
                for (int nt = 0; nt < 8; nt++) {
                    MMA_BF16(acc[mt][nt], ahi[mt], &bhi[nt*2]);
                    MMA_BF16(acc[mt][nt], ahi[mt], &blo[nt*2]);
                    MMA_BF16(acc[mt][nt], alo[mt], &bhi[nt*2]);
                }
        }
    }

    #pragma unroll
    for (int mt = 0; mt < 2; mt++) {
        const int r0 = row0 + warp_m*32 + mt*16 + (lane >> 2);
        const int r1 = r0 + 8;
        const int bb0 = r0 / RPB, cc0 = r0 - bb0 * RPB;
        const int bb1 = r1 / RPB, cc1 = r1 - bb1 * RPB;
        #pragma unroll
        for (int nt = 0; nt < 8; nt++) {
            const int o = nb + warp_n*64 + nt*8 + (lane & 3)*2;
            const int h = o >> 5, d = o & 31;
            const float2 bv = *(const float2*)&bias[o];
            float2 v0 = make_float2(acc[mt][nt][0] + bv.x, acc[mt][nt][1] + bv.y);
            float2 v1 = make_float2(acc[mt][nt][2] + bv.x, acc[mt][nt][3] + bv.y);
            *(float2*)&Y[(((long long)bb0 * NH + h) * RPB + cc0) * DK + d] = v0;
            *(float2*)&Y[(((long long)bb1 * NH + h) * RPB + cc1) * DK + d] = v1;
        }
    }
}

// ---------------- attention: full-mma, fragment-resident --------------------
// Block = one (b,h). 8 warps = 4(M: 64 rows, 50 used) x 2(N: 104 cols each).
// S = q_hat @ k_hat^T via bf16-split mma; softmax on fragments (quad shuffles
// + cross-warp smem exchange); att fragments repacked in-registers as A of
// the AV mma (P-reuse); V^T fragments via ldmatrix.trans.
// smem offsets (bytes):
#define ATT_QHI 0
#define ATT_QLO 5120
#define ATT_KHI 10240     // 224 rows x 80B
#define ATT_KLO 28160
#define ATT_VHI 46080     // 208 rows x 80B
#define ATT_VLO 62720
#define ATT_PB  79360     // 200 f32
#define ATT_RMX 80160     // [64][2] f32
#define ATT_RSM 80672     // [64][2] f32
#define ATT_ORD 81184     // [64][36] f32
#define ATT_SMEM 90400

__global__ __launch_bounds__(256)
void att_mma(const float* __restrict__ pos_bias,
             float* __restrict__ att_out, int write_att)
{
    extern __shared__ char sm[];
    const uint32_t base = smem_u32(sm);
    __nv_bfloat16* smQhi = (__nv_bfloat16*)(sm + ATT_QHI);
    __nv_bfloat16* smQlo = (__nv_bfloat16*)(sm + ATT_QLO);
    __nv_bfloat16* smKhi = (__nv_bfloat16*)(sm + ATT_KHI);
    __nv_bfloat16* smKlo = (__nv_bfloat16*)(sm + ATT_KLO);
    __nv_bfloat16* smVhi = (__nv_bfloat16*)(sm + ATT_VHI);
    __nv_bfloat16* smVlo = (__nv_bfloat16*)(sm + ATT_VLO);
    float* spb  = (float*)(sm + ATT_PB);
    float* srmx = (float*)(sm + ATT_RMX);
    float* srsm = (float*)(sm + ATT_RSM);
    float* sord = (float*)(sm + ATT_ORD);

    const int bh = blockIdx.x;
    const int b  = bh >> 3;
    const int h  = bh & 7;
    const int tid  = threadIdx.x;
    const int wid  = tid >> 5;
    const int lane = tid & 31;
    const int warp_m = wid & 3;
    const int warp_n = wid >> 2;

    // ---- load q (rows 0..63; >=NT zero-filled), normalized, bf16 hi/lo ----
    if (tid < 64) {
        float4 qr[8];
        float sc = 0.f;
        if (tid < NT) {
            const float4* qg = (const float4*)(g_qh + ((long long)bh*NT + tid)*DK);
            float ss = 0.f;
            #pragma unroll
            for (int j = 0; j < 8; j++) {
                qr[j] = qg[j];
                ss += qr[j].x*qr[j].x + qr[j].y*qr[j].y + qr[j].z*qr[j].z + qr[j].w*qr[j].w;
            }
            sc = rsqrtf(fmaxf(ss, 1e-24f));
        } else {
            #pragma unroll
            for (int j = 0; j < 8; j++) qr[j] = make_float4(0.f,0.f,0.f,0.f);
        }
        #pragma unroll
        for (int j = 0; j < 8; j++) {
            uint32_t h0,l0,h1,l1;
            pack_hilo(qr[j].x*sc, qr[j].y*sc, h0, l0);
            pack_hilo(qr[j].z*sc, qr[j].w*sc, h1, l1);
            *(uint2*)&smQhi[tid*40 + j*4] = make_uint2(h0, h1);
            *(uint2*)&smQlo[tid*40 + j*4] = make_uint2(l0, l1);
        }
    }
    // ---- load k rows 0..199, normalized ----
    if (tid < WINDOW) {
        const float4* kg = (const float4*)(g_kh + ((long long)bh*WINDOW + tid)*DK);
        float4 kr[8];
        float ss = 0.f;
        #pragma unroll
        for (int j = 0; j < 8; j++) {
            kr[j] = kg[j];
            ss += kr[j].x*kr[j].x + kr[j].y*kr[j].y + kr[j].z*kr[j].z + kr[j].w*kr[j].w;
        }
        const float sc = rsqrtf(fmaxf(ss, 1e-24f));
        #pragma unroll
        for (int j = 0; j < 8; j++) {
            uint32_t h0,l0,h1,l1;
            pack_hilo(kr[j].x*sc, kr[j].y*sc, h0, l0);
            pack_hilo(kr[j].z*sc, kr[j].w*sc, h1, l1);
            *(uint2*)&smKhi[tid*40 + j*4] = make_uint2(h0, h1);
            *(uint2*)&smKlo[tid*40 + j*4] = make_uint2(l0, l1);
        }
        spb[tid] = pos_bias[tid];
    }
    // ---- load v [c][d] bf16 hi/lo (no norm) ----
    {
        const float4* vg = (const float4*)(g_vp + (long long)bh*WINDOW*DK);
        #pragma unroll
        for (int i = 0; i < 7; i++) {
            int idx = tid + i * 256;
            if (idx < 1600) {
                int c = idx >> 3, dg = idx & 7;
                float4 x = vg[idx];
                uint32_t h0,l0,h1,l1;
                pack_hilo(x.x, x.y, h0, l0);
                pack_hilo(x.z, x.w, h1, l1);
                *(uint2*)&smVhi[c*40 + dg*4] = make_uint2(h0, h1);
                *(uint2*)&smVlo[c*40 + dg*4] = make_uint2(l0, l1);
            }
        }
    }
    __syncthreads();

    const int lr = lane & 7;
    const int lq = lane >> 3;
    const int nbase = warp_n * 104;

    // ---- score mma: S[64 x 104] per warp-pair ----
    const uint32_t aoff = (uint32_t)((warp_m*16 + lr + 8*(lq & 1)) * 80 + (lq >> 1) * 16);
    uint32_t qhiF[2][4], qloF[2][4];
    LDSM_X4(qhiF[0], base + ATT_QHI + aoff);
    LDSM_X4(qhiF[1], base + ATT_QHI + aoff + 32);
    LDSM_X4(qloF[0], base + ATT_QLO + aoff);
    LDSM_X4(qloF[1], base + ATT_QLO + aoff + 32);

    float S[13][4];
    #pragma unroll
    for (int nt = 0; nt < 13; nt++)
        #pragma unroll
        for (int j = 0; j < 4; j++) S[nt][j] = 0.f;

    const uint32_t boffK = (uint32_t)((nbase + lr + 8*(lq >> 1)) * 80 + (lq & 1) * 16);
    #pragma unroll
    for (int p = 0; p < 7; p++) {
        uint32_t Bh0[4], Bh1[4], Bl0[4], Bl1[4];
        LDSM_X4(Bh0, base + ATT_KHI + boffK + p*16*80);
        LDSM_X4(Bh1, base + ATT_KHI + boffK + p*16*80 + 32);
        LDSM_X4(Bl0, base + ATT_KLO + boffK + p*16*80);
        LDSM_X4(Bl1, base + ATT_KLO + boffK + p*16*80 + 32);
        #pragma unroll
        for (int s = 0; s < 2; s++) {
            const int nt = 2*p + s;
            if (nt > 12) break;
            MMA_BF16(S[nt], qhiF[0], &Bh0[s*2]);
            MMA_BF16(S[nt], qhiF[1], &Bh1[s*2]);
            MMA_BF16(S[nt], qhiF[0], &Bl0[s*2]);
            MMA_BF16(S[nt], qhiF[1], &Bl1[s*2]);
            MMA_BF16(S[nt], qloF[0], &Bh0[s*2]);
            MMA_BF16(S[nt], qloF[1], &Bh1[s*2]);
        }
    }

    // ---- softmax on fragments ----
    const int r0 = warp_m*16 + (lane >> 2);   // global row (t), second row r0+8
    float mx0 = -3e38f, mx1 = -3e38f;
    #pragma unroll
    for (int nt = 0; nt < 13; nt++) {
        if (warp_n == 1 && nt == 12) {
            S[nt][0] = S[nt][1] = S[nt][2] = S[nt][3] = -1e30f;
        } else {
            const int c = nbase + nt*8 + (lane & 3)*2;
            float2 pb2 = *(float2*)&spb[c];
            S[nt][0] += pb2.x; S[nt][1] += pb2.y;
            S[nt][2] += pb2.x; S[nt][3] += pb2.y;
        }
        mx0 = fmaxf(mx0, fmaxf(S[nt][0], S[nt][1]));
        mx1 = fmaxf(mx1, fmaxf(S[nt][2], S[nt][3]));
    }
    mx0 = fmaxf(mx0, __shfl_xor_sync(0xffffffffu, mx0, 1));
    mx0 = fmaxf(mx0, __shfl_xor_sync(0xffffffffu, mx0, 2));
    mx1 = fmaxf(mx1, __shfl_xor_sync(0xffffffffu, mx1, 1));
    mx1 = fmaxf(mx1, __shfl_xor_sync(0xffffffffu, mx1, 2));
    if ((lane & 3) == 0) {
        srmx[r0*2 + warp_n]     = mx0;
        srmx[(r0+8)*2 + warp_n] = mx1;
    }
    __syncthreads();
    mx0 = fmaxf(srmx[r0*2],     srmx[r0*2 + 1]);
    mx1 = fmaxf(srmx[(r0+8)*2], srmx[(r0+8)*2 + 1]);

    float sm0 = 0.f, sm1 = 0.f;
    #pragma unroll
    for (int nt = 0; nt < 13; nt++) {
        S[nt][0] = __expf(S[nt][0] - mx0);
        S[nt][1] = __expf(S[nt][1] - mx0);
        S[nt][2] = __expf(S[nt][2] - mx1);
        S[nt][3] = __expf(S[nt][3] - mx1);
        sm0 += S[nt][0] + S[nt][1];
        sm1 += S[nt][2] + S[nt][3];
    }
    sm0 += __shfl_xor_sync(0xffffffffu, sm0, 1);
    sm0 += __shfl_xor_sync(0xffffffffu, sm0, 2);
    sm1 += __shfl_xor_sync(0xffffffffu, sm1, 1);
    sm1 += __shfl_xor_sync(0xffffffffu, sm1, 2);
    if ((lane & 3) == 0) {
        srsm[r0*2 + warp_n]     = sm0;
        srsm[(r0+8)*2 + warp_n] = sm1;
    }
    __syncthreads();
    const float inv0 = 1.0f / (srsm[r0*2]     + srsm[r0*2 + 1]);
    const float inv1 = 1.0f / (srsm[(r0+8)*2] + srsm[(r0+8)*2 + 1]);
    #pragma unroll
    for (int nt = 0; nt < 13; nt++) {
        S[nt][0] *= inv0; S[nt][1] *= inv0;
        S[nt][2] *= inv1; S[nt][3] *= inv1;
    }

    // ---- write att to gmem directly from fragments ----
    if (write_att) {
        float* ab = att_out + (long long)bh * NT * WINDOW;
        #pragma unroll
        for (int nt = 0; nt < 13; nt++) {
            if (warp_n == 1 && nt == 12) continue;
            const int c = nbase + nt*8 + (lane & 3)*2;
            if (r0 < NT)
                *(float2*)&ab[r0*WINDOW + c]     = make_float2(S[nt][0], S[nt][1]);
            if (r0 + 8 < NT)
                *(float2*)&ab[(r0+8)*WINDOW + c] = make_float2(S[nt][2], S[nt][3]);
        }
    }

    // ---- AV mma: out[64x32] partial over this warp's 104 cols ----
    float O[4][4];
    #pragma unroll
    for (int j = 0; j < 4; j++)
        #pragma unroll
        for (int i = 0; i < 4; i++) O[j][i] = 0.f;

    const uint32_t voff = (uint32_t)(((lq & 1)*8 + lr) * 80 + (lq >> 1) * 16);
    #pragma unroll
    for (int q = 0; q < 7; q++) {
        if (q == 6 && warp_n == 1) break;
        const int kc = nbase + q*16;
        uint32_t vh0[4], vh1[4], vl0[4], vl1[4];
        LDSM_X4_T(vh0, base + ATT_VHI + voff + kc*80);       // d 0..15
        LDSM_X4_T(vh1, base + ATT_VHI + voff + kc*80 + 32);  // d 16..31
        LDSM_X4_T(vl0, base + ATT_VLO + voff + kc*80);
        LDSM_X4_T(vl1, base + ATT_VLO + voff + kc*80 + 32);

        uint32_t ahi[4], alo[4];
        const int tA = 2*q, tB = 2*q + 1;
        pack_hilo(S[tA][0], S[tA][1], ahi[0], alo[0]);
        pack_hilo(S[tA][2], S[tA][3], ahi[1], alo[1]);
        if (tB <= 12) {
            pack_hilo(S[tB][0], S[tB][1], ahi[2], alo[2]);
            pack_hilo(S[tB][2], S[tB][3], ahi[3], alo[3]);
        } else {
            ahi[2] = ahi[3] = alo[2] = alo[3] = 0u;
        }
        MMA_BF16(O[0], ahi, &vh0[0]); MMA_BF16(O[0], ahi, &vl0[0]); MMA_BF16(O[0], alo, &vh0[0]);
        MMA_BF16(O[1], ahi, &vh0[2]); MMA_BF16(O[1], ahi, &vl0[2]); MMA_BF16(O[1], alo, &vh0[2]);
        MMA_BF16(O[2], ahi, &vh1[0]); MMA_BF16(O[2], ahi, &vl1[0]); MMA_BF16(O[2], alo, &vh1[0]);
        MMA_BF16(O[3], ahi, &vh1[2]); MMA_BF16(O[3], ahi, &vl1[2]); MMA_BF16(O[3], alo, &vh1[2]);
    }

    // ---- combine the 2 N-half partials, write g_oh ----
    if (warp_n == 0) {
        #pragma unroll
        for (int j = 0; j < 4; j++) {
            const int d = j*8 + (lane & 3)*2;
            *(float2*)&sord[r0*36 + d]     = make_float2(O[j][0], O[j][1]);
            *(float2*)&sord[(r0+8)*36 + d] = make_float2(O[j][2], O[j][3]);
        }
    }
    __syncthreads();
    if (warp_n == 1) {
        #pragma unroll
        for (int j = 0; j < 4; j++) {
            const int d = j*8 + (lane & 3)*2;
            if (r0 < NT) {
                float2 p = *(float2*)&sord[r0*36 + d];
                *(float2*)&g_oh[((long long)b*NT + r0)*256 + h*32 + d] =
                    make_float2(p.x + O[j][0], p.y + O[j][1]);
            }
            if (r0 + 8 < NT) {
                float2 p = *(float2*)&sord[(r0+8)*36 + d];
                *(float2*)&g_oh[((long long)b*NT + r0 + 8)*256 + h*32 + d] =
                    make_float2(p.x + O[j][2], p.y + O[j][3]);
            }
        }
    }
}

// ---------------- final projection: out = oh @ R^T + Rb --------------------
__global__ __launch_bounds__(256)
void out_kernel(const float* __restrict__ Rb, float* __restrict__ out)
{
    __shared__ float sx[25 * 256];
    __shared__ float pbuf[25 * 128];
    const int row0 = blockIdx.x * 25;

    const float4* xg = (const float4*)(g_oh + (long long)row0 * 256);
    float4* sx4 = (float4*)sx;
    #pragma unroll
    for (int i = 0; i < 7; i++) {
        int idx = threadIdx.x + i * 256;
        if (idx < 1600) sx4[idx] = xg[idx];
    }
    __syncthreads();

    const int e    = threadIdx.x & 127;
    const int half = threadIdx.x >> 7;
    float2 acc[25];
    #pragma unroll
    for (int r = 0; r < 25; r++) acc[r] = make_float2(0.f, 0.f);

    const int k0 = half * 128;
    for (int k = 0; k < 128; k += 4) {
        const int kk = k0 + k;
        float w0 = g_rt[(kk+0)*128 + e];
        float w1 = g_rt[(kk+1)*128 + e];
        float w2 = g_rt[(kk+2)*128 + e];
        float w3 = g_rt[(kk+3)*128 + e];
        float2 wab = make_float2(w0, w1), wcd = make_float2(w2, w3);
        #pragma unroll
        for (int r = 0; r < 25; r++) {
            float4 x4 = *(const float4*)&sx[r*256 + kk];
            acc[r] = ffma2(make_float2(x4.x, x4.y), wab, acc[r]);
            acc[r] = ffma2(make_float2(x4.z, x4.w), wcd, acc[r]);
        }
    }

    if (half == 1) {
        #pragma unroll
        for (int r = 0; r < 25; r++) pbuf[r*128 + e] = acc[r].x + acc[r].y;
    }
    __syncthreads();
    if (half == 0) {
        const float bo = Rb[e];
        #pragma unroll
        for (int r = 0; r < 25; r++) {
            out[(long long)(row0 + r) * 128 + e] =
                acc[r].x + acc[r].y + pbuf[r*128 + e] + bo;
        }
    }
}

// ---------------- launch ----------------------------------------------------
extern "C" void kernel_launch(void* const* d_in, const int* in_sizes, int n_in,
                              void* d_out, int out_size)
{
    const float* queries  = (const float*)d_in[0];
    const float* keys     = (const float*)d_in[1];
    const float* values   = (const float*)d_in[2];
    const float* At_w     = (const float*)d_in[3];
    const float* At_b     = (const float*)d_in[4];
    const float* Ac_w     = (const float*)d_in[5];
    const float* Ac_b     = (const float*)d_in[6];
    const float* Bc_w     = (const float*)d_in[7];
    const float* Bc_b     = (const float*)d_in[8];
    const float* pos_bias = (const float*)d_in[9];
    const float* R_w      = (const float*)d_in[10];
    const float* R_b      = (const float*)d_in[11];
    float* out = (float*)d_out;

    cudaFuncSetAttribute(att_mma,
        cudaFuncAttributeMaxDynamicSharedMemorySize, ATT_SMEM);

    prep_w<<<128, 256>>>(At_w, Ac_w, Bc_w, R_w);

    proj_mma<NT,     0><<<dim3(NB*NT/128,     2), 256>>>(queries, At_b, 0);
    proj_mma<WINDOW, 1><<<dim3(NB*WINDOW/128, 2), 256>>>(keys,    Ac_b, 1);
    proj_mma<WINDOW, 2><<<dim3(NB*WINDOW/128, 2), 256>>>(values,  Bc_b, 2);

    const long long need = (long long)OUT_ELEMS + (long long)ATT_ELEMS;
    const int write_att = ((long long)out_size >= need) ? 1 : 0;
    att_mma<<<NB*NH, 256, ATT_SMEM>>>(pos_bias, out + OUT_ELEMS, write_att);

    out_kernel<<<NB*NT/25, 256>>>(R_b, out);
}